// round 1
// baseline (speedup 1.0000x reference)
#include <cuda_runtime.h>
#include <cuda_bf16.h>
#include <math.h>

#define T_ 2048
#define N_ 2
#define C_ 1024
#define H_ 16
#define DH_ 64
#define M_ (T_ * N_)
#define WINDOW_ 128
#define SCALE_ 0.125f

__device__ float g_qh[N_ * H_ * T_ * DH_];
__device__ float g_kh[N_ * H_ * T_ * DH_];
__device__ float g_vh[N_ * H_ * T_ * DH_];
__device__ float g_att[T_ * N_ * C_];

// ---------------------------------------------------------------------------
// Projection GEMM: out[r,o] = sum_c A[r,c]*W[o,c] + b[o]
// ---------------------------------------------------------------------------
__global__ __launch_bounds__(256) void proj_kernel(
    const float* __restrict__ q, const float* __restrict__ k, const float* __restrict__ v,
    const float* __restrict__ Wq, const float* __restrict__ bq,
    const float* __restrict__ Wk, const float* __restrict__ bk,
    const float* __restrict__ Wv, const float* __restrict__ bv)
{
    const int which = blockIdx.z;
    const float* A    = (which == 0) ? q  : (which == 1) ? k  : v;
    const float* B    = (which == 0) ? Wq : (which == 1) ? Wk : Wv;
    const float* bias = (which == 0) ? bq : (which == 1) ? bk : bv;
    float* out        = (which == 0) ? g_qh : (which == 1) ? g_kh : g_vh;

    __shared__ float As[16][132];
    __shared__ float Bs[16][68];

    const int tid = threadIdx.x;
    const int ty = tid >> 4, tx = tid & 15;
    const int r0 = blockIdx.y * 128;
    const int c0 = blockIdx.x * 64;
    const int lrow = tid >> 2;
    const int lk4  = tid & 3;

    float acc[8][4];
#pragma unroll
    for (int i = 0; i < 8; i++)
#pragma unroll
        for (int j = 0; j < 4; j++) acc[i][j] = 0.f;

    for (int k0 = 0; k0 < C_; k0 += 16) {
#pragma unroll
        for (int half = 0; half < 2; half++) {
            int r = lrow + half * 64;
            float4 a4 = *reinterpret_cast<const float4*>(A + (size_t)(r0 + r) * C_ + k0 + lk4 * 4);
            As[lk4 * 4 + 0][r] = a4.x;
            As[lk4 * 4 + 1][r] = a4.y;
            As[lk4 * 4 + 2][r] = a4.z;
            As[lk4 * 4 + 3][r] = a4.w;
        }
        {
            float4 b4 = *reinterpret_cast<const float4*>(B + (size_t)(c0 + lrow) * C_ + k0 + lk4 * 4);
            Bs[lk4 * 4 + 0][lrow] = b4.x;
            Bs[lk4 * 4 + 1][lrow] = b4.y;
            Bs[lk4 * 4 + 2][lrow] = b4.z;
            Bs[lk4 * 4 + 3][lrow] = b4.w;
        }
        __syncthreads();
#pragma unroll
        for (int kk = 0; kk < 16; kk++) {
            float a[8], bb[4];
#pragma unroll
            for (int i = 0; i < 8; i++) a[i] = As[kk][ty * 8 + i];
#pragma unroll
            for (int j = 0; j < 4; j++) bb[j] = Bs[kk][tx * 4 + j];
#pragma unroll
            for (int i = 0; i < 8; i++)
#pragma unroll
                for (int j = 0; j < 4; j++) acc[i][j] = fmaf(a[i], bb[j], acc[i][j]);
        }
        __syncthreads();
    }

#pragma unroll
    for (int i = 0; i < 8; i++) {
        int gr = r0 + ty * 8 + i;
        int t = gr >> 1, n = gr & 1;
#pragma unroll
        for (int j = 0; j < 4; j++) {
            int gc = c0 + tx * 4 + j;
            int h = gc >> 6, d = gc & 63;
            out[(((size_t)(n * H_ + h) * T_) + t) * DH_ + d] = acc[i][j] + bias[gc];
        }
    }
}

// ---------------------------------------------------------------------------
// Output projection
// ---------------------------------------------------------------------------
__global__ __launch_bounds__(256) void outproj_kernel(
    const float* __restrict__ Wo, const float* __restrict__ bo, float* __restrict__ out)
{
    __shared__ float As[16][132];
    __shared__ float Bs[16][68];

    const int tid = threadIdx.x;
    const int ty = tid >> 4, tx = tid & 15;
    const int r0 = blockIdx.y * 128;
    const int c0 = blockIdx.x * 64;
    const int lrow = tid >> 2;
    const int lk4  = tid & 3;

    float acc[8][4];
#pragma unroll
    for (int i = 0; i < 8; i++)
#pragma unroll
        for (int j = 0; j < 4; j++) acc[i][j] = 0.f;

    for (int k0 = 0; k0 < C_; k0 += 16) {
#pragma unroll
        for (int half = 0; half < 2; half++) {
            int r = lrow + half * 64;
            float4 a4 = *reinterpret_cast<const float4*>(g_att + (size_t)(r0 + r) * C_ + k0 + lk4 * 4);
            As[lk4 * 4 + 0][r] = a4.x;
            As[lk4 * 4 + 1][r] = a4.y;
            As[lk4 * 4 + 2][r] = a4.z;
            As[lk4 * 4 + 3][r] = a4.w;
        }
        {
            float4 b4 = *reinterpret_cast<const float4*>(Wo + (size_t)(c0 + lrow) * C_ + k0 + lk4 * 4);
            Bs[lk4 * 4 + 0][lrow] = b4.x;
            Bs[lk4 * 4 + 1][lrow] = b4.y;
            Bs[lk4 * 4 + 2][lrow] = b4.z;
            Bs[lk4 * 4 + 3][lrow] = b4.w;
        }
        __syncthreads();
#pragma unroll
        for (int kk = 0; kk < 16; kk++) {
            float a[8], bb[4];
#pragma unroll
            for (int i = 0; i < 8; i++) a[i] = As[kk][ty * 8 + i];
#pragma unroll
            for (int j = 0; j < 4; j++) bb[j] = Bs[kk][tx * 4 + j];
#pragma unroll
            for (int i = 0; i < 8; i++)
#pragma unroll
                for (int j = 0; j < 4; j++) acc[i][j] = fmaf(a[i], bb[j], acc[i][j]);
        }
        __syncthreads();
    }

#pragma unroll
    for (int i = 0; i < 8; i++) {
        int gr = r0 + ty * 8 + i;
#pragma unroll
        for (int j = 0; j < 4; j++) {
            int gc = c0 + tx * 4 + j;
            out[(size_t)gr * C_ + gc] = acc[i][j] + bo[gc];
        }
    }
}

// ---------------------------------------------------------------------------
// Flash attention with mask-based tile skipping
// ---------------------------------------------------------------------------
__global__ __launch_bounds__(256) void attn_kernel(const int* __restrict__ key_length)
{
    extern __shared__ float sm[];
    float* Qs = sm;                 // [64][68], [d][i]
    float* Ks = Qs + 64 * 68;       // [64][68], [d][j]
    float* Vs = Ks + 64 * 68;       // [64][68], [j][d]
    float* Ps = Vs + 64 * 68;       // [64][68], [j][i]

    const int n = blockIdx.z;
    const int h = blockIdx.y;
    const int i0 = blockIdx.x * 64;
    const int kl = key_length[n];

    const int tid = threadIdx.x;
    const int ty = tid >> 4, tx = tid & 15;

    const float* Qg = g_qh + (size_t)(n * H_ + h) * T_ * DH_;
    const float* Kg = g_kh + (size_t)(n * H_ + h) * T_ * DH_;
    const float* Vg = g_vh + (size_t)(n * H_ + h) * T_ * DH_;

#pragma unroll
    for (int it = 0; it < 4; it++) {
        int idx = tid + it * 256;
        int row = idx >> 4;
        int d4 = idx & 15;
        float4 qv = *reinterpret_cast<const float4*>(Qg + (size_t)(i0 + row) * DH_ + d4 * 4);
        Qs[(d4 * 4 + 0) * 68 + row] = qv.x;
        Qs[(d4 * 4 + 1) * 68 + row] = qv.y;
        Qs[(d4 * 4 + 2) * 68 + row] = qv.z;
        Qs[(d4 * 4 + 3) * 68 + row] = qv.w;
    }

    float acc[4][4];
    float m_i[4], l_i[4];
#pragma unroll
    for (int ii = 0; ii < 4; ii++) {
        m_i[ii] = -INFINITY;
        l_i[ii] = 0.f;
#pragma unroll
        for (int dd = 0; dd < 4; dd++) acc[ii][dd] = 0.f;
    }

    for (int j0 = 0; j0 < T_; j0 += 64) {
        bool band = (j0 <= i0 + 63 + WINDOW_) && (j0 + 63 >= i0 - WINDOW_);
        if (!(band || j0 < kl)) continue;

        __syncthreads();

#pragma unroll
        for (int it = 0; it < 4; it++) {
            int idx = tid + it * 256;
            int row = idx >> 4;
            int d4 = idx & 15;
            float4 kv = *reinterpret_cast<const float4*>(Kg + (size_t)(j0 + row) * DH_ + d4 * 4);
            Ks[(d4 * 4 + 0) * 68 + row] = kv.x;
            Ks[(d4 * 4 + 1) * 68 + row] = kv.y;
            Ks[(d4 * 4 + 2) * 68 + row] = kv.z;
            Ks[(d4 * 4 + 3) * 68 + row] = kv.w;
            float4 vv = *reinterpret_cast<const float4*>(Vg + (size_t)(j0 + row) * DH_ + d4 * 4);
            *reinterpret_cast<float4*>(Vs + row * 68 + d4 * 4) = vv;
        }
        __syncthreads();

        float s[4][4];
#pragma unroll
        for (int ii = 0; ii < 4; ii++)
#pragma unroll
            for (int jj = 0; jj < 4; jj++) s[ii][jj] = 0.f;
#pragma unroll 8
        for (int d = 0; d < 64; d++) {
            float a[4], b[4];
#pragma unroll
            for (int ii = 0; ii < 4; ii++) a[ii] = Qs[d * 68 + ty * 4 + ii];
#pragma unroll
            for (int jj = 0; jj < 4; jj++) b[jj] = Ks[d * 68 + tx * 4 + jj];
#pragma unroll
            for (int ii = 0; ii < 4; ii++)
#pragma unroll
                for (int jj = 0; jj < 4; jj++) s[ii][jj] = fmaf(a[ii], b[jj], s[ii][jj]);
        }

#pragma unroll
        for (int ii = 0; ii < 4; ii++) {
            int i = i0 + ty * 4 + ii;
#pragma unroll
            for (int jj = 0; jj < 4; jj++) {
                int j = j0 + tx * 4 + jj;
                bool ok = (j < kl) || (j - i <= WINDOW_ && i - j <= WINDOW_);
                s[ii][jj] = ok ? s[ii][jj] * SCALE_ : -1e9f;
            }
        }

        float mt[4];
#pragma unroll
        for (int ii = 0; ii < 4; ii++)
            mt[ii] = fmaxf(fmaxf(s[ii][0], s[ii][1]), fmaxf(s[ii][2], s[ii][3]));
#pragma unroll
        for (int off = 1; off < 16; off <<= 1) {
#pragma unroll
            for (int ii = 0; ii < 4; ii++)
                mt[ii] = fmaxf(mt[ii], __shfl_xor_sync(0xffffffffu, mt[ii], off));
        }

        float corr[4];
#pragma unroll
        for (int ii = 0; ii < 4; ii++) {
            float mn = fmaxf(m_i[ii], mt[ii]);
            corr[ii] = __expf(m_i[ii] - mn);
            m_i[ii] = mn;
        }

        float rs[4] = {0.f, 0.f, 0.f, 0.f};
#pragma unroll
        for (int ii = 0; ii < 4; ii++) {
#pragma unroll
            for (int jj = 0; jj < 4; jj++) {
                float p = __expf(s[ii][jj] - m_i[ii]);
                Ps[(tx * 4 + jj) * 68 + ty * 4 + ii] = p;
                rs[ii] += p;
            }
        }
#pragma unroll
        for (int off = 1; off < 16; off <<= 1) {
#pragma unroll
            for (int ii = 0; ii < 4; ii++)
                rs[ii] += __shfl_xor_sync(0xffffffffu, rs[ii], off);
        }
#pragma unroll
        for (int ii = 0; ii < 4; ii++) {
            l_i[ii] = l_i[ii] * corr[ii] + rs[ii];
#pragma unroll
            for (int dd = 0; dd < 4; dd++) acc[ii][dd] *= corr[ii];
        }

        __syncthreads();

#pragma unroll 8
        for (int j = 0; j < 64; j++) {
            float a[4], b[4];
#pragma unroll
            for (int ii = 0; ii < 4; ii++) a[ii] = Ps[j * 68 + ty * 4 + ii];
#pragma unroll
            for (int dd = 0; dd < 4; dd++) b[dd] = Vs[j * 68 + tx * 4 + dd];
#pragma unroll
            for (int ii = 0; ii < 4; ii++)
#pragma unroll
                for (int dd = 0; dd < 4; dd++) acc[ii][dd] = fmaf(a[ii], b[dd], acc[ii][dd]);
        }
    }

#pragma unroll
    for (int ii = 0; ii < 4; ii++) {
        int i = i0 + ty * 4 + ii;
        float inv = 1.f / l_i[ii];
#pragma unroll
        for (int dd = 0; dd < 4; dd++) {
            int dg = tx * 4 + dd;
            g_att[((size_t)i * N_ + n) * C_ + h * DH_ + dg] = acc[ii][dd] * inv;
        }
    }
}

extern "C" void kernel_launch(void* const* d_in, const int* in_sizes, int n_in,
                              void* d_out, int out_size)
{
    const float* q  = (const float*)d_in[0];
    const float* k  = (const float*)d_in[1];
    const float* v  = (const float*)d_in[2];
    const float* Wq = (const float*)d_in[3];
    const float* bq = (const float*)d_in[4];
    const float* Wk = (const float*)d_in[5];
    const float* bk = (const float*)d_in[6];
    const float* Wv = (const float*)d_in[7];
    const float* bv = (const float*)d_in[8];
    const float* Wo = (const float*)d_in[9];
    const float* bo = (const float*)d_in[10];
    const int* key_length = (const int*)d_in[11];
    float* out = (float*)d_out;

    dim3 gproj(C_ / 64, M_ / 128, 3);
    proj_kernel<<<gproj, 256>>>(q, k, v, Wq, bq, Wk, bk, Wv, bv);

    const int attn_smem = 4 * 64 * 68 * (int)sizeof(float);
    cudaFuncSetAttribute(attn_kernel, cudaFuncAttributeMaxDynamicSharedMemorySize, attn_smem);
    dim3 gattn(T_ / 64, H_, N_);
    attn_kernel<<<gattn, 256, attn_smem>>>(key_length);

    dim3 gout(C_ / 64, M_ / 128);
    outproj_kernel<<<gout, 256>>>(Wo, bo, out);
}

// round 2
// speedup vs baseline: 1.0827x; 1.0827x over previous
#include <cuda_runtime.h>
#include <cuda_bf16.h>
#include <math.h>

#define T_ 2048
#define N_ 2
#define C_ 1024
#define H_ 16
#define DH_ 64
#define M_ (T_ * N_)
#define WINDOW_ 128
#define SCALE_ 0.125f

__device__ float g_qh[N_ * H_ * T_ * DH_];
__device__ float g_kh[N_ * H_ * T_ * DH_];
__device__ float g_vh[N_ * H_ * T_ * DH_];
__device__ float g_att[T_ * N_ * C_];

// ---------------------------------------------------------------------------
// Projection GEMM: out[r,o] = sum_c A[r,c]*W[o,c] + b[o]
// 128x128 tile, 256 threads, 8x8 per thread (split 4+4 in each dim).
// ---------------------------------------------------------------------------
__global__ __launch_bounds__(256) void proj_kernel(
    const float* __restrict__ q, const float* __restrict__ k, const float* __restrict__ v,
    const float* __restrict__ Wq, const float* __restrict__ bq,
    const float* __restrict__ Wk, const float* __restrict__ bk,
    const float* __restrict__ Wv, const float* __restrict__ bv)
{
    const int which = blockIdx.z;
    const float* A    = (which == 0) ? q  : (which == 1) ? k  : v;
    const float* B    = (which == 0) ? Wq : (which == 1) ? Wk : Wv;
    const float* bias = (which == 0) ? bq : (which == 1) ? bk : bv;
    float* out        = (which == 0) ? g_qh : (which == 1) ? g_kh : g_vh;

    __shared__ float As[16][132];
    __shared__ float Bs[16][132];

    const int tid = threadIdx.x;
    const int ty = tid >> 4, tx = tid & 15;
    const int r0 = blockIdx.y * 128;
    const int c0 = blockIdx.x * 128;

    float acc[8][8];
#pragma unroll
    for (int i = 0; i < 8; i++)
#pragma unroll
        for (int j = 0; j < 8; j++) acc[i][j] = 0.f;

    for (int k0 = 0; k0 < C_; k0 += 16) {
#pragma unroll
        for (int s = 0; s < 2; s++) {
            int idx = tid + s * 256;       // 0..511
            int row = idx >> 2;            // 0..127
            int qq  = idx & 3;             // float4 group in K
            float4 a4 = *reinterpret_cast<const float4*>(A + (size_t)(r0 + row) * C_ + k0 + qq * 4);
            As[qq * 4 + 0][row] = a4.x;
            As[qq * 4 + 1][row] = a4.y;
            As[qq * 4 + 2][row] = a4.z;
            As[qq * 4 + 3][row] = a4.w;
            float4 b4 = *reinterpret_cast<const float4*>(B + (size_t)(c0 + row) * C_ + k0 + qq * 4);
            Bs[qq * 4 + 0][row] = b4.x;
            Bs[qq * 4 + 1][row] = b4.y;
            Bs[qq * 4 + 2][row] = b4.z;
            Bs[qq * 4 + 3][row] = b4.w;
        }
        __syncthreads();
#pragma unroll
        for (int kk = 0; kk < 16; kk++) {
            float4 a0 = *reinterpret_cast<const float4*>(&As[kk][ty * 4]);
            float4 a1 = *reinterpret_cast<const float4*>(&As[kk][64 + ty * 4]);
            float4 b0 = *reinterpret_cast<const float4*>(&Bs[kk][tx * 4]);
            float4 b1 = *reinterpret_cast<const float4*>(&Bs[kk][64 + tx * 4]);
            float a[8] = {a0.x, a0.y, a0.z, a0.w, a1.x, a1.y, a1.z, a1.w};
            float bb[8] = {b0.x, b0.y, b0.z, b0.w, b1.x, b1.y, b1.z, b1.w};
#pragma unroll
            for (int i = 0; i < 8; i++)
#pragma unroll
                for (int j = 0; j < 8; j++) acc[i][j] = fmaf(a[i], bb[j], acc[i][j]);
        }
        __syncthreads();
    }

    // Epilogue: scatter to (n,h,t,d); cols contiguous in groups of 4 within a head
#pragma unroll
    for (int ih = 0; ih < 2; ih++) {
#pragma unroll
        for (int i = 0; i < 4; i++) {
            int gr = r0 + ih * 64 + ty * 4 + i;
            int t = gr >> 1, n = gr & 1;
#pragma unroll
            for (int jh = 0; jh < 2; jh++) {
                int gc = c0 + jh * 64 + tx * 4;
                int h = gc >> 6, d = gc & 63;
                float4 o;
                o.x = acc[ih * 4 + i][jh * 4 + 0] + bias[gc + 0];
                o.y = acc[ih * 4 + i][jh * 4 + 1] + bias[gc + 1];
                o.z = acc[ih * 4 + i][jh * 4 + 2] + bias[gc + 2];
                o.w = acc[ih * 4 + i][jh * 4 + 3] + bias[gc + 3];
                *reinterpret_cast<float4*>(out + (((size_t)(n * H_ + h) * T_) + t) * DH_ + d) = o;
            }
        }
    }
}

// ---------------------------------------------------------------------------
// Output projection: same tiling, row-major epilogue
// ---------------------------------------------------------------------------
__global__ __launch_bounds__(256) void outproj_kernel(
    const float* __restrict__ Wo, const float* __restrict__ bo, float* __restrict__ out)
{
    __shared__ float As[16][132];
    __shared__ float Bs[16][132];

    const int tid = threadIdx.x;
    const int ty = tid >> 4, tx = tid & 15;
    const int r0 = blockIdx.y * 128;
    const int c0 = blockIdx.x * 128;

    float acc[8][8];
#pragma unroll
    for (int i = 0; i < 8; i++)
#pragma unroll
        for (int j = 0; j < 8; j++) acc[i][j] = 0.f;

    for (int k0 = 0; k0 < C_; k0 += 16) {
#pragma unroll
        for (int s = 0; s < 2; s++) {
            int idx = tid + s * 256;
            int row = idx >> 2;
            int qq  = idx & 3;
            float4 a4 = *reinterpret_cast<const float4*>(g_att + (size_t)(r0 + row) * C_ + k0 + qq * 4);
            As[qq * 4 + 0][row] = a4.x;
            As[qq * 4 + 1][row] = a4.y;
            As[qq * 4 + 2][row] = a4.z;
            As[qq * 4 + 3][row] = a4.w;
            float4 b4 = *reinterpret_cast<const float4*>(Wo + (size_t)(c0 + row) * C_ + k0 + qq * 4);
            Bs[qq * 4 + 0][row] = b4.x;
            Bs[qq * 4 + 1][row] = b4.y;
            Bs[qq * 4 + 2][row] = b4.z;
            Bs[qq * 4 + 3][row] = b4.w;
        }
        __syncthreads();
#pragma unroll
        for (int kk = 0; kk < 16; kk++) {
            float4 a0 = *reinterpret_cast<const float4*>(&As[kk][ty * 4]);
            float4 a1 = *reinterpret_cast<const float4*>(&As[kk][64 + ty * 4]);
            float4 b0 = *reinterpret_cast<const float4*>(&Bs[kk][tx * 4]);
            float4 b1 = *reinterpret_cast<const float4*>(&Bs[kk][64 + tx * 4]);
            float a[8] = {a0.x, a0.y, a0.z, a0.w, a1.x, a1.y, a1.z, a1.w};
            float bb[8] = {b0.x, b0.y, b0.z, b0.w, b1.x, b1.y, b1.z, b1.w};
#pragma unroll
            for (int i = 0; i < 8; i++)
#pragma unroll
                for (int j = 0; j < 8; j++) acc[i][j] = fmaf(a[i], bb[j], acc[i][j]);
        }
        __syncthreads();
    }

#pragma unroll
    for (int ih = 0; ih < 2; ih++) {
#pragma unroll
        for (int i = 0; i < 4; i++) {
            int gr = r0 + ih * 64 + ty * 4 + i;
#pragma unroll
            for (int jh = 0; jh < 2; jh++) {
                int gc = c0 + jh * 64 + tx * 4;
                float4 o;
                o.x = acc[ih * 4 + i][jh * 4 + 0] + bo[gc + 0];
                o.y = acc[ih * 4 + i][jh * 4 + 1] + bo[gc + 1];
                o.z = acc[ih * 4 + i][jh * 4 + 2] + bo[gc + 2];
                o.w = acc[ih * 4 + i][jh * 4 + 3] + bo[gc + 3];
                *reinterpret_cast<float4*>(out + (size_t)gr * C_ + gc) = o;
            }
        }
    }
}

// ---------------------------------------------------------------------------
// Flash attention, 64x64 tiles, 128 threads, 8 rows x 4 cols per thread.
// ty = tid>>4 (0..7): rows {ty*4..+3} and {32+ty*4..+3}. tx = tid&15: cols tx*4..+3.
// ---------------------------------------------------------------------------
__global__ __launch_bounds__(128) void attn_kernel(const int* __restrict__ key_length)
{
    extern __shared__ float sm[];
    float* Qs = sm;                 // [d][i] stride 68
    float* Ks = Qs + 64 * 68;       // [d][j] stride 68
    float* Vs = Ks + 64 * 68;       // [j][d] stride 68
    float* Ps = Vs + 64 * 68;       // [i][j] stride 68

    const int n = blockIdx.z;
    const int h = blockIdx.y;
    const int i0 = blockIdx.x * 64;
    const int kl = key_length[n];

    const int tid = threadIdx.x;
    const int ty = tid >> 4, tx = tid & 15;

    const float* Qg = g_qh + (size_t)(n * H_ + h) * T_ * DH_;
    const float* Kg = g_kh + (size_t)(n * H_ + h) * T_ * DH_;
    const float* Vg = g_vh + (size_t)(n * H_ + h) * T_ * DH_;

    // Load Q tile transposed: 1024 float4, 8 per thread
#pragma unroll
    for (int it = 0; it < 8; it++) {
        int idx = tid + it * 128;
        int row = idx >> 4;
        int d4 = idx & 15;
        float4 qv = *reinterpret_cast<const float4*>(Qg + (size_t)(i0 + row) * DH_ + d4 * 4);
        Qs[(d4 * 4 + 0) * 68 + row] = qv.x;
        Qs[(d4 * 4 + 1) * 68 + row] = qv.y;
        Qs[(d4 * 4 + 2) * 68 + row] = qv.z;
        Qs[(d4 * 4 + 3) * 68 + row] = qv.w;
    }

    float acc[8][4];
    float m_i[8], l_i[8];
#pragma unroll
    for (int ii = 0; ii < 8; ii++) {
        m_i[ii] = -INFINITY;
        l_i[ii] = 0.f;
#pragma unroll
        for (int dd = 0; dd < 4; dd++) acc[ii][dd] = 0.f;
    }

    for (int j0 = 0; j0 < T_; j0 += 64) {
        bool band = (j0 <= i0 + 63 + WINDOW_) && (j0 + 63 >= i0 - WINDOW_);
        if (!(band || j0 < kl)) continue;

        __syncthreads();

        // Load K (transposed) and V (natural)
#pragma unroll
        for (int it = 0; it < 8; it++) {
            int idx = tid + it * 128;
            int row = idx >> 4;
            int d4 = idx & 15;
            float4 kv = *reinterpret_cast<const float4*>(Kg + (size_t)(j0 + row) * DH_ + d4 * 4);
            Ks[(d4 * 4 + 0) * 68 + row] = kv.x;
            Ks[(d4 * 4 + 1) * 68 + row] = kv.y;
            Ks[(d4 * 4 + 2) * 68 + row] = kv.z;
            Ks[(d4 * 4 + 3) * 68 + row] = kv.w;
            float4 vv = *reinterpret_cast<const float4*>(Vg + (size_t)(j0 + row) * DH_ + d4 * 4);
            *reinterpret_cast<float4*>(Vs + row * 68 + d4 * 4) = vv;
        }
        __syncthreads();

        // S = Q K^T : 8 rows x 4 cols per thread
        float s[8][4];
#pragma unroll
        for (int ii = 0; ii < 8; ii++)
#pragma unroll
            for (int jj = 0; jj < 4; jj++) s[ii][jj] = 0.f;

#pragma unroll 4
        for (int d = 0; d < 64; d++) {
            float4 a0 = *reinterpret_cast<const float4*>(&Qs[d * 68 + ty * 4]);
            float4 a1 = *reinterpret_cast<const float4*>(&Qs[d * 68 + 32 + ty * 4]);
            float4 b  = *reinterpret_cast<const float4*>(&Ks[d * 68 + tx * 4]);
            float a[8] = {a0.x, a0.y, a0.z, a0.w, a1.x, a1.y, a1.z, a1.w};
            float bb[4] = {b.x, b.y, b.z, b.w};
#pragma unroll
            for (int ii = 0; ii < 8; ii++)
#pragma unroll
                for (int jj = 0; jj < 4; jj++) s[ii][jj] = fmaf(a[ii], bb[jj], s[ii][jj]);
        }

        // Mask + scale
#pragma unroll
        for (int ii = 0; ii < 8; ii++) {
            int i = i0 + ((ii < 4) ? (ty * 4 + ii) : (32 + ty * 4 + ii - 4));
#pragma unroll
            for (int jj = 0; jj < 4; jj++) {
                int j = j0 + tx * 4 + jj;
                bool ok = (j < kl) || (j - i <= WINDOW_ && i - j <= WINDOW_);
                s[ii][jj] = ok ? s[ii][jj] * SCALE_ : -1e9f;
            }
        }

        // Row max (local then across 16 tx lanes)
        float mt[8];
#pragma unroll
        for (int ii = 0; ii < 8; ii++)
            mt[ii] = fmaxf(fmaxf(s[ii][0], s[ii][1]), fmaxf(s[ii][2], s[ii][3]));
#pragma unroll
        for (int off = 1; off < 16; off <<= 1) {
#pragma unroll
            for (int ii = 0; ii < 8; ii++)
                mt[ii] = fmaxf(mt[ii], __shfl_xor_sync(0xffffffffu, mt[ii], off));
        }

        float corr[8];
#pragma unroll
        for (int ii = 0; ii < 8; ii++) {
            float mn = fmaxf(m_i[ii], mt[ii]);
            corr[ii] = __expf(m_i[ii] - mn);
            m_i[ii] = mn;
        }

        // P = exp(S - m); store to Ps[i][j] (float4, conflict-free); rowsum
        float rs[8];
#pragma unroll
        for (int ii = 0; ii < 8; ii++) {
            int i_loc = (ii < 4) ? (ty * 4 + ii) : (32 + ty * 4 + ii - 4);
            float4 p4;
            p4.x = __expf(s[ii][0] - m_i[ii]);
            p4.y = __expf(s[ii][1] - m_i[ii]);
            p4.z = __expf(s[ii][2] - m_i[ii]);
            p4.w = __expf(s[ii][3] - m_i[ii]);
            *reinterpret_cast<float4*>(&Ps[i_loc * 68 + tx * 4]) = p4;
            rs[ii] = p4.x + p4.y + p4.z + p4.w;
        }
#pragma unroll
        for (int off = 1; off < 16; off <<= 1) {
#pragma unroll
            for (int ii = 0; ii < 8; ii++)
                rs[ii] += __shfl_xor_sync(0xffffffffu, rs[ii], off);
        }
#pragma unroll
        for (int ii = 0; ii < 8; ii++) {
            l_i[ii] = l_i[ii] * corr[ii] + rs[ii];
#pragma unroll
            for (int dd = 0; dd < 4; dd++) acc[ii][dd] *= corr[ii];
        }

        __syncthreads();   // Ps fully written

        // O += P @ V : process 4 j per step, float4 loads of P rows
#pragma unroll 2
        for (int j4 = 0; j4 < 16; j4++) {
            float4 pa[8];
#pragma unroll
            for (int ii = 0; ii < 8; ii++) {
                int i_loc = (ii < 4) ? (ty * 4 + ii) : (32 + ty * 4 + ii - 4);
                pa[ii] = *reinterpret_cast<const float4*>(&Ps[i_loc * 68 + j4 * 4]);
            }
#pragma unroll
            for (int ju = 0; ju < 4; ju++) {
                float4 b = *reinterpret_cast<const float4*>(&Vs[(j4 * 4 + ju) * 68 + tx * 4]);
                float pv[8] = {pa[0].x, pa[1].x, pa[2].x, pa[3].x, pa[4].x, pa[5].x, pa[6].x, pa[7].x};
                // select component ju
                if (ju == 1) { pv[0]=pa[0].y; pv[1]=pa[1].y; pv[2]=pa[2].y; pv[3]=pa[3].y; pv[4]=pa[4].y; pv[5]=pa[5].y; pv[6]=pa[6].y; pv[7]=pa[7].y; }
                else if (ju == 2) { pv[0]=pa[0].z; pv[1]=pa[1].z; pv[2]=pa[2].z; pv[3]=pa[3].z; pv[4]=pa[4].z; pv[5]=pa[5].z; pv[6]=pa[6].z; pv[7]=pa[7].z; }
                else if (ju == 3) { pv[0]=pa[0].w; pv[1]=pa[1].w; pv[2]=pa[2].w; pv[3]=pa[3].w; pv[4]=pa[4].w; pv[5]=pa[5].w; pv[6]=pa[6].w; pv[7]=pa[7].w; }
#pragma unroll
                for (int ii = 0; ii < 8; ii++) {
                    acc[ii][0] = fmaf(pv[ii], b.x, acc[ii][0]);
                    acc[ii][1] = fmaf(pv[ii], b.y, acc[ii][1]);
                    acc[ii][2] = fmaf(pv[ii], b.z, acc[ii][2]);
                    acc[ii][3] = fmaf(pv[ii], b.w, acc[ii][3]);
                }
            }
        }
    }

    // Epilogue: divide by l, write to (t,n,c)
#pragma unroll
    for (int ii = 0; ii < 8; ii++) {
        int i_loc = (ii < 4) ? (ty * 4 + ii) : (32 + ty * 4 + ii - 4);
        int i = i0 + i_loc;
        float inv = 1.f / l_i[ii];
        float4 o;
        o.x = acc[ii][0] * inv;
        o.y = acc[ii][1] * inv;
        o.z = acc[ii][2] * inv;
        o.w = acc[ii][3] * inv;
        *reinterpret_cast<float4*>(g_att + ((size_t)i * N_ + n) * C_ + h * DH_ + tx * 4) = o;
    }
}

extern "C" void kernel_launch(void* const* d_in, const int* in_sizes, int n_in,
                              void* d_out, int out_size)
{
    const float* q  = (const float*)d_in[0];
    const float* k  = (const float*)d_in[1];
    const float* v  = (const float*)d_in[2];
    const float* Wq = (const float*)d_in[3];
    const float* bq = (const float*)d_in[4];
    const float* Wk = (const float*)d_in[5];
    const float* bk = (const float*)d_in[6];
    const float* Wv = (const float*)d_in[7];
    const float* bv = (const float*)d_in[8];
    const float* Wo = (const float*)d_in[9];
    const float* bo = (const float*)d_in[10];
    const int* key_length = (const int*)d_in[11];
    float* out = (float*)d_out;

    dim3 gproj(C_ / 128, M_ / 128, 3);
    proj_kernel<<<gproj, 256>>>(q, k, v, Wq, bq, Wk, bk, Wv, bv);

    const int attn_smem = 4 * 64 * 68 * (int)sizeof(float);   // 69632 B
    cudaFuncSetAttribute(attn_kernel, cudaFuncAttributeMaxDynamicSharedMemorySize, attn_smem);
    dim3 gattn(T_ / 64, H_, N_);
    attn_kernel<<<gattn, 128, attn_smem>>>(key_length);

    dim3 gout(C_ / 128, M_ / 128);
    outproj_kernel<<<gout, 256>>>(Wo, bo, out);
}

// round 3
// speedup vs baseline: 1.4896x; 1.3759x over previous
#include <cuda_runtime.h>
#include <cuda_bf16.h>
#include <math.h>

#define T_ 2048
#define N_ 2
#define C_ 1024
#define H_ 16
#define DH_ 64
#define M_ (T_ * N_)
#define WINDOW_ 128
#define SCALE_ 0.125f

typedef unsigned int u32;

__device__ float g_qh[N_ * H_ * T_ * DH_];
__device__ float g_kh[N_ * H_ * T_ * DH_];
__device__ float g_vh[N_ * H_ * T_ * DH_];
__device__ float g_att[T_ * N_ * C_];

// ---------------------------------------------------------------------------
// bf16 split helpers
// ---------------------------------------------------------------------------
__device__ __forceinline__ void cvt_pair(float x, float y, u32& hi, u32& lo) {
    __nv_bfloat16 hx = __float2bfloat16_rn(x);
    __nv_bfloat16 hy = __float2bfloat16_rn(y);
    float rx = x - __bfloat162float(hx);
    float ry = y - __bfloat162float(hy);
    __nv_bfloat16 lx = __float2bfloat16_rn(rx);
    __nv_bfloat16 ly = __float2bfloat16_rn(ry);
    __nv_bfloat162 H; H.x = hx; H.y = hy;
    __nv_bfloat162 L; L.x = lx; L.y = ly;
    hi = *reinterpret_cast<u32*>(&H);
    lo = *reinterpret_cast<u32*>(&L);
}

__device__ __forceinline__ void mma16816(float& c0, float& c1, float& c2, float& c3,
                                         u32 a0, u32 a1, u32 a2, u32 a3, u32 b0, u32 b1) {
    asm volatile(
        "mma.sync.aligned.m16n8k16.row.col.f32.bf16.bf16.f32 "
        "{%0,%1,%2,%3}, {%4,%5,%6,%7}, {%8,%9}, {%0,%1,%2,%3};\n"
        : "+f"(c0), "+f"(c1), "+f"(c2), "+f"(c3)
        : "r"(a0), "r"(a1), "r"(a2), "r"(a3), "r"(b0), "r"(b1));
}

// ---------------------------------------------------------------------------
// Tensor-core GEMM body: C[128x128] tile of  out[r,o] = sum_c A[r,c]*W[o,c]
// BK=32. Smem pair-arrays stride 20 u32 (16 used) -> conflict-free frag loads.
// 8 warps: warp_m = wid>>2 (64 rows), warp_n = wid&3 (32 cols).
// acc[mt][nt][4], mt<4 (16 rows), nt<4 (8 cols).
// ---------------------------------------------------------------------------
#define LDSTRIDE 20

struct GemmSmem {
    u32 AsH[128 * LDSTRIDE];
    u32 AsL[128 * LDSTRIDE];
    u32 BsH[128 * LDSTRIDE];
    u32 BsL[128 * LDSTRIDE];
};

__device__ __forceinline__ void gemm_tile_tc(
    const float* __restrict__ A, const float* __restrict__ B,
    int r0, int c0, GemmSmem& S, float acc[4][4][4])
{
    const int tid = threadIdx.x;
    const int wid = tid >> 5;
    const int lane = tid & 31;
    const int g = lane >> 2;      // group 0..7
    const int t = lane & 3;       // thread-in-group
    const int warp_m = (wid >> 2) * 64;
    const int warp_n = (wid & 3) * 32;

#pragma unroll
    for (int mt = 0; mt < 4; mt++)
#pragma unroll
        for (int nt = 0; nt < 4; nt++)
#pragma unroll
            for (int r = 0; r < 4; r++) acc[mt][nt][r] = 0.f;

    for (int k0 = 0; k0 < C_; k0 += 32) {
        __syncthreads();
        // Load + convert A and B tiles: 128 rows x 32 cols each.
#pragma unroll
        for (int s = 0; s < 4; s++) {
            int idx = tid + s * 256;          // 0..1023
            int row = idx >> 3;               // 0..127
            int f4 = idx & 7;                 // 0..7
            float4 a4 = *reinterpret_cast<const float4*>(A + (size_t)(r0 + row) * C_ + k0 + f4 * 4);
            u32 h0, l0, h1, l1;
            cvt_pair(a4.x, a4.y, h0, l0);
            cvt_pair(a4.z, a4.w, h1, l1);
            int base = row * LDSTRIDE + f4 * 2;
            S.AsH[base] = h0; S.AsH[base + 1] = h1;
            S.AsL[base] = l0; S.AsL[base + 1] = l1;
            float4 b4 = *reinterpret_cast<const float4*>(B + (size_t)(c0 + row) * C_ + k0 + f4 * 4);
            cvt_pair(b4.x, b4.y, h0, l0);
            cvt_pair(b4.z, b4.w, h1, l1);
            S.BsH[base] = h0; S.BsH[base + 1] = h1;
            S.BsL[base] = l0; S.BsL[base + 1] = l1;
        }
        __syncthreads();

#pragma unroll
        for (int kk = 0; kk < 2; kk++) {
            const int ko = kk * 8;
            u32 ah[4][4], bh[4][2];
            // A_hi frags
#pragma unroll
            for (int mt = 0; mt < 4; mt++) {
                int m = warp_m + mt * 16;
                ah[mt][0] = S.AsH[(m + g) * LDSTRIDE + ko + t];
                ah[mt][1] = S.AsH[(m + g + 8) * LDSTRIDE + ko + t];
                ah[mt][2] = S.AsH[(m + g) * LDSTRIDE + ko + t + 4];
                ah[mt][3] = S.AsH[(m + g + 8) * LDSTRIDE + ko + t + 4];
            }
            // B_hi frags
#pragma unroll
            for (int nt = 0; nt < 4; nt++) {
                int n = warp_n + nt * 8;
                bh[nt][0] = S.BsH[(n + g) * LDSTRIDE + ko + t];
                bh[nt][1] = S.BsH[(n + g) * LDSTRIDE + ko + t + 4];
            }
            // hi*hi
#pragma unroll
            for (int mt = 0; mt < 4; mt++)
#pragma unroll
                for (int nt = 0; nt < 4; nt++)
                    mma16816(acc[mt][nt][0], acc[mt][nt][1], acc[mt][nt][2], acc[mt][nt][3],
                             ah[mt][0], ah[mt][1], ah[mt][2], ah[mt][3], bh[nt][0], bh[nt][1]);
            // hi*lo
            {
                u32 bl[4][2];
#pragma unroll
                for (int nt = 0; nt < 4; nt++) {
                    int n = warp_n + nt * 8;
                    bl[nt][0] = S.BsL[(n + g) * LDSTRIDE + ko + t];
                    bl[nt][1] = S.BsL[(n + g) * LDSTRIDE + ko + t + 4];
                }
#pragma unroll
                for (int mt = 0; mt < 4; mt++)
#pragma unroll
                    for (int nt = 0; nt < 4; nt++)
                        mma16816(acc[mt][nt][0], acc[mt][nt][1], acc[mt][nt][2], acc[mt][nt][3],
                                 ah[mt][0], ah[mt][1], ah[mt][2], ah[mt][3], bl[nt][0], bl[nt][1]);
            }
            // lo*hi
            {
                u32 al[4][4];
#pragma unroll
                for (int mt = 0; mt < 4; mt++) {
                    int m = warp_m + mt * 16;
                    al[mt][0] = S.AsL[(m + g) * LDSTRIDE + ko + t];
                    al[mt][1] = S.AsL[(m + g + 8) * LDSTRIDE + ko + t];
                    al[mt][2] = S.AsL[(m + g) * LDSTRIDE + ko + t + 4];
                    al[mt][3] = S.AsL[(m + g + 8) * LDSTRIDE + ko + t + 4];
                }
#pragma unroll
                for (int mt = 0; mt < 4; mt++)
#pragma unroll
                    for (int nt = 0; nt < 4; nt++)
                        mma16816(acc[mt][nt][0], acc[mt][nt][1], acc[mt][nt][2], acc[mt][nt][3],
                                 al[mt][0], al[mt][1], al[mt][2], al[mt][3], bh[nt][0], bh[nt][1]);
            }
        }
    }
}

// ---------------------------------------------------------------------------
// QKV projections (blockIdx.z selects). Epilogue scatters to (n,h,t,d).
// ---------------------------------------------------------------------------
__global__ __launch_bounds__(256, 1) void proj_kernel_tc(
    const float* __restrict__ q, const float* __restrict__ k, const float* __restrict__ v,
    const float* __restrict__ Wq, const float* __restrict__ bq,
    const float* __restrict__ Wk, const float* __restrict__ bk,
    const float* __restrict__ Wv, const float* __restrict__ bv)
{
    const int which = blockIdx.z;
    const float* A    = (which == 0) ? q  : (which == 1) ? k  : v;
    const float* B    = (which == 0) ? Wq : (which == 1) ? Wk : Wv;
    const float* bias = (which == 0) ? bq : (which == 1) ? bk : bv;
    float* out        = (which == 0) ? g_qh : (which == 1) ? g_kh : g_vh;

    __shared__ GemmSmem S;
    const int r0 = blockIdx.y * 128;
    const int c0 = blockIdx.x * 128;

    float acc[4][4][4];
    gemm_tile_tc(A, B, r0, c0, S, acc);

    const int tid = threadIdx.x;
    const int wid = tid >> 5;
    const int lane = tid & 31;
    const int g = lane >> 2;
    const int t = lane & 3;
    const int warp_m = (wid >> 2) * 64;
    const int warp_n = (wid & 3) * 32;

#pragma unroll
    for (int mt = 0; mt < 4; mt++) {
#pragma unroll
        for (int nt = 0; nt < 4; nt++) {
            int gc = c0 + warp_n + nt * 8 + 2 * t;
            int h = gc >> 6, d = gc & 63;
            float bx = bias[gc], by = bias[gc + 1];
#pragma unroll
            for (int half = 0; half < 2; half++) {
                int gr = r0 + warp_m + mt * 16 + g + half * 8;
                int tt = gr >> 1, n = gr & 1;
                float2 o;
                o.x = acc[mt][nt][half * 2 + 0] + bx;
                o.y = acc[mt][nt][half * 2 + 1] + by;
                *reinterpret_cast<float2*>(out + (((size_t)(n * H_ + h) * T_) + tt) * DH_ + d) = o;
            }
        }
    }
}

// ---------------------------------------------------------------------------
// Output projection; row-major epilogue to d_out.
// ---------------------------------------------------------------------------
__global__ __launch_bounds__(256, 1) void outproj_kernel_tc(
    const float* __restrict__ Wo, const float* __restrict__ bo, float* __restrict__ out)
{
    __shared__ GemmSmem S;
    const int r0 = blockIdx.y * 128;
    const int c0 = blockIdx.x * 128;

    float acc[4][4][4];
    gemm_tile_tc(g_att, Wo, r0, c0, S, acc);

    const int tid = threadIdx.x;
    const int wid = tid >> 5;
    const int lane = tid & 31;
    const int g = lane >> 2;
    const int t = lane & 3;
    const int warp_m = (wid >> 2) * 64;
    const int warp_n = (wid & 3) * 32;

#pragma unroll
    for (int mt = 0; mt < 4; mt++) {
#pragma unroll
        for (int nt = 0; nt < 4; nt++) {
            int gc = c0 + warp_n + nt * 8 + 2 * t;
            float bx = bo[gc], by = bo[gc + 1];
#pragma unroll
            for (int half = 0; half < 2; half++) {
                int gr = r0 + warp_m + mt * 16 + g + half * 8;
                float2 o;
                o.x = acc[mt][nt][half * 2 + 0] + bx;
                o.y = acc[mt][nt][half * 2 + 1] + by;
                *reinterpret_cast<float2*>(out + (size_t)gr * C_ + gc) = o;
            }
        }
    }
}

// ---------------------------------------------------------------------------
// Flash attention (unchanged from R2)
// ---------------------------------------------------------------------------
__global__ __launch_bounds__(128) void attn_kernel(const int* __restrict__ key_length)
{
    extern __shared__ float sm[];
    float* Qs = sm;
    float* Ks = Qs + 64 * 68;
    float* Vs = Ks + 64 * 68;
    float* Ps = Vs + 64 * 68;

    const int n = blockIdx.z;
    const int h = blockIdx.y;
    const int i0 = blockIdx.x * 64;
    const int kl = key_length[n];

    const int tid = threadIdx.x;
    const int ty = tid >> 4, tx = tid & 15;

    const float* Qg = g_qh + (size_t)(n * H_ + h) * T_ * DH_;
    const float* Kg = g_kh + (size_t)(n * H_ + h) * T_ * DH_;
    const float* Vg = g_vh + (size_t)(n * H_ + h) * T_ * DH_;

#pragma unroll
    for (int it = 0; it < 8; it++) {
        int idx = tid + it * 128;
        int row = idx >> 4;
        int d4 = idx & 15;
        float4 qv = *reinterpret_cast<const float4*>(Qg + (size_t)(i0 + row) * DH_ + d4 * 4);
        Qs[(d4 * 4 + 0) * 68 + row] = qv.x;
        Qs[(d4 * 4 + 1) * 68 + row] = qv.y;
        Qs[(d4 * 4 + 2) * 68 + row] = qv.z;
        Qs[(d4 * 4 + 3) * 68 + row] = qv.w;
    }

    float acc[8][4];
    float m_i[8], l_i[8];
#pragma unroll
    for (int ii = 0; ii < 8; ii++) {
        m_i[ii] = -INFINITY;
        l_i[ii] = 0.f;
#pragma unroll
        for (int dd = 0; dd < 4; dd++) acc[ii][dd] = 0.f;
    }

    for (int j0 = 0; j0 < T_; j0 += 64) {
        bool band = (j0 <= i0 + 63 + WINDOW_) && (j0 + 63 >= i0 - WINDOW_);
        if (!(band || j0 < kl)) continue;

        __syncthreads();

#pragma unroll
        for (int it = 0; it < 8; it++) {
            int idx = tid + it * 128;
            int row = idx >> 4;
            int d4 = idx & 15;
            float4 kv = *reinterpret_cast<const float4*>(Kg + (size_t)(j0 + row) * DH_ + d4 * 4);
            Ks[(d4 * 4 + 0) * 68 + row] = kv.x;
            Ks[(d4 * 4 + 1) * 68 + row] = kv.y;
            Ks[(d4 * 4 + 2) * 68 + row] = kv.z;
            Ks[(d4 * 4 + 3) * 68 + row] = kv.w;
            float4 vv = *reinterpret_cast<const float4*>(Vg + (size_t)(j0 + row) * DH_ + d4 * 4);
            *reinterpret_cast<float4*>(Vs + row * 68 + d4 * 4) = vv;
        }
        __syncthreads();

        float s[8][4];
#pragma unroll
        for (int ii = 0; ii < 8; ii++)
#pragma unroll
            for (int jj = 0; jj < 4; jj++) s[ii][jj] = 0.f;

#pragma unroll 4
        for (int d = 0; d < 64; d++) {
            float4 a0 = *reinterpret_cast<const float4*>(&Qs[d * 68 + ty * 4]);
            float4 a1 = *reinterpret_cast<const float4*>(&Qs[d * 68 + 32 + ty * 4]);
            float4 b  = *reinterpret_cast<const float4*>(&Ks[d * 68 + tx * 4]);
            float a[8] = {a0.x, a0.y, a0.z, a0.w, a1.x, a1.y, a1.z, a1.w};
            float bb[4] = {b.x, b.y, b.z, b.w};
#pragma unroll
            for (int ii = 0; ii < 8; ii++)
#pragma unroll
                for (int jj = 0; jj < 4; jj++) s[ii][jj] = fmaf(a[ii], bb[jj], s[ii][jj]);
        }

#pragma unroll
        for (int ii = 0; ii < 8; ii++) {
            int i = i0 + ((ii < 4) ? (ty * 4 + ii) : (32 + ty * 4 + ii - 4));
#pragma unroll
            for (int jj = 0; jj < 4; jj++) {
                int j = j0 + tx * 4 + jj;
                bool ok = (j < kl) || (j - i <= WINDOW_ && i - j <= WINDOW_);
                s[ii][jj] = ok ? s[ii][jj] * SCALE_ : -1e9f;
            }
        }

        float mt[8];
#pragma unroll
        for (int ii = 0; ii < 8; ii++)
            mt[ii] = fmaxf(fmaxf(s[ii][0], s[ii][1]), fmaxf(s[ii][2], s[ii][3]));
#pragma unroll
        for (int off = 1; off < 16; off <<= 1) {
#pragma unroll
            for (int ii = 0; ii < 8; ii++)
                mt[ii] = fmaxf(mt[ii], __shfl_xor_sync(0xffffffffu, mt[ii], off));
        }

        float corr[8];
#pragma unroll
        for (int ii = 0; ii < 8; ii++) {
            float mn = fmaxf(m_i[ii], mt[ii]);
            corr[ii] = __expf(m_i[ii] - mn);
            m_i[ii] = mn;
        }

        float rs[8];
#pragma unroll
        for (int ii = 0; ii < 8; ii++) {
            int i_loc = (ii < 4) ? (ty * 4 + ii) : (32 + ty * 4 + ii - 4);
            float4 p4;
            p4.x = __expf(s[ii][0] - m_i[ii]);
            p4.y = __expf(s[ii][1] - m_i[ii]);
            p4.z = __expf(s[ii][2] - m_i[ii]);
            p4.w = __expf(s[ii][3] - m_i[ii]);
            *reinterpret_cast<float4*>(&Ps[i_loc * 68 + tx * 4]) = p4;
            rs[ii] = p4.x + p4.y + p4.z + p4.w;
        }
#pragma unroll
        for (int off = 1; off < 16; off <<= 1) {
#pragma unroll
            for (int ii = 0; ii < 8; ii++)
                rs[ii] += __shfl_xor_sync(0xffffffffu, rs[ii], off);
        }
#pragma unroll
        for (int ii = 0; ii < 8; ii++) {
            l_i[ii] = l_i[ii] * corr[ii] + rs[ii];
#pragma unroll
            for (int dd = 0; dd < 4; dd++) acc[ii][dd] *= corr[ii];
        }

        __syncthreads();

#pragma unroll 2
        for (int j4 = 0; j4 < 16; j4++) {
            float4 pa[8];
#pragma unroll
            for (int ii = 0; ii < 8; ii++) {
                int i_loc = (ii < 4) ? (ty * 4 + ii) : (32 + ty * 4 + ii - 4);
                pa[ii] = *reinterpret_cast<const float4*>(&Ps[i_loc * 68 + j4 * 4]);
            }
#pragma unroll
            for (int ju = 0; ju < 4; ju++) {
                float4 b = *reinterpret_cast<const float4*>(&Vs[(j4 * 4 + ju) * 68 + tx * 4]);
                float pv[8] = {pa[0].x, pa[1].x, pa[2].x, pa[3].x, pa[4].x, pa[5].x, pa[6].x, pa[7].x};
                if (ju == 1) { pv[0]=pa[0].y; pv[1]=pa[1].y; pv[2]=pa[2].y; pv[3]=pa[3].y; pv[4]=pa[4].y; pv[5]=pa[5].y; pv[6]=pa[6].y; pv[7]=pa[7].y; }
                else if (ju == 2) { pv[0]=pa[0].z; pv[1]=pa[1].z; pv[2]=pa[2].z; pv[3]=pa[3].z; pv[4]=pa[4].z; pv[5]=pa[5].z; pv[6]=pa[6].z; pv[7]=pa[7].z; }
                else if (ju == 3) { pv[0]=pa[0].w; pv[1]=pa[1].w; pv[2]=pa[2].w; pv[3]=pa[3].w; pv[4]=pa[4].w; pv[5]=pa[5].w; pv[6]=pa[6].w; pv[7]=pa[7].w; }
#pragma unroll
                for (int ii = 0; ii < 8; ii++) {
                    acc[ii][0] = fmaf(pv[ii], b.x, acc[ii][0]);
                    acc[ii][1] = fmaf(pv[ii], b.y, acc[ii][1]);
                    acc[ii][2] = fmaf(pv[ii], b.z, acc[ii][2]);
                    acc[ii][3] = fmaf(pv[ii], b.w, acc[ii][3]);
                }
            }
        }
    }

#pragma unroll
    for (int ii = 0; ii < 8; ii++) {
        int i_loc = (ii < 4) ? (ty * 4 + ii) : (32 + ty * 4 + ii - 4);
        int i = i0 + i_loc;
        float inv = 1.f / l_i[ii];
        float4 o;
        o.x = acc[ii][0] * inv;
        o.y = acc[ii][1] * inv;
        o.z = acc[ii][2] * inv;
        o.w = acc[ii][3] * inv;
        *reinterpret_cast<float4*>(g_att + ((size_t)i * N_ + n) * C_ + h * DH_ + tx * 4) = o;
    }
}

extern "C" void kernel_launch(void* const* d_in, const int* in_sizes, int n_in,
                              void* d_out, int out_size)
{
    const float* q  = (const float*)d_in[0];
    const float* k  = (const float*)d_in[1];
    const float* v  = (const float*)d_in[2];
    const float* Wq = (const float*)d_in[3];
    const float* bq = (const float*)d_in[4];
    const float* Wk = (const float*)d_in[5];
    const float* bk = (const float*)d_in[6];
    const float* Wv = (const float*)d_in[7];
    const float* bv = (const float*)d_in[8];
    const float* Wo = (const float*)d_in[9];
    const float* bo = (const float*)d_in[10];
    const int* key_length = (const int*)d_in[11];
    float* out = (float*)d_out;

    dim3 gproj(C_ / 128, M_ / 128, 3);
    proj_kernel_tc<<<gproj, 256>>>(q, k, v, Wq, bq, Wk, bk, Wv, bv);

    const int attn_smem = 4 * 64 * 68 * (int)sizeof(float);
    cudaFuncSetAttribute(attn_kernel, cudaFuncAttributeMaxDynamicSharedMemorySize, attn_smem);
    dim3 gattn(T_ / 64, H_, N_);
    attn_kernel<<<gattn, 128, attn_smem>>>(key_length);

    dim3 gout(C_ / 128, M_ / 128);
    outproj_kernel_tc<<<gout, 256>>>(Wo, bo, out);
}

// round 5
// speedup vs baseline: 1.6678x; 1.1196x over previous
#include <cuda_runtime.h>
#include <cuda_bf16.h>
#include <math.h>

#define T_ 2048
#define N_ 2
#define C_ 1024
#define H_ 16
#define DH_ 64
#define M_ (T_ * N_)
#define WINDOW_ 128
#define SCALE_ 0.125f

typedef unsigned int u32;

// fp32 intermediates
__device__ __align__(16) float g_qh[N_ * H_ * T_ * DH_];
__device__ __align__(16) float g_kh[N_ * H_ * T_ * DH_];
__device__ __align__(16) float g_vh[N_ * H_ * T_ * DH_];

// Pre-converted bf16 hi/lo pool: [q | k | v | Wq | Wk | Wv | Wo]
#define OFF_Q  0
#define OFF_K  4194304
#define OFF_V  8388608
#define OFF_WQ 12582912
#define OFF_WK 13631488
#define OFF_WV 14680064
#define OFF_WO 15728640
#define TOTAL_CVT 16777216
__device__ __align__(16) __nv_bfloat16 g_hi[TOTAL_CVT];
__device__ __align__(16) __nv_bfloat16 g_lo[TOTAL_CVT];

// attention output, bf16 hi/lo (row-major 4096 x 1024, row = t*2+n)
__device__ __align__(16) __nv_bfloat16 g_attH[M_ * C_];
__device__ __align__(16) __nv_bfloat16 g_attL[M_ * C_];

// ---------------------------------------------------------------------------
// helpers
// ---------------------------------------------------------------------------
__device__ __forceinline__ void cvt_pair(float x, float y, u32& hi, u32& lo) {
    __nv_bfloat16 hx = __float2bfloat16_rn(x);
    __nv_bfloat16 hy = __float2bfloat16_rn(y);
    float rx = x - __bfloat162float(hx);
    float ry = y - __bfloat162float(hy);
    __nv_bfloat16 lx = __float2bfloat16_rn(rx);
    __nv_bfloat16 ly = __float2bfloat16_rn(ry);
    __nv_bfloat162 Hh; Hh.x = hx; Hh.y = hy;
    __nv_bfloat162 Ll; Ll.x = lx; Ll.y = ly;
    hi = *reinterpret_cast<u32*>(&Hh);
    lo = *reinterpret_cast<u32*>(&Ll);
}

__device__ __forceinline__ void mma16816(float& c0, float& c1, float& c2, float& c3,
                                         u32 a0, u32 a1, u32 a2, u32 a3, u32 b0, u32 b1) {
    asm volatile(
        "mma.sync.aligned.m16n8k16.row.col.f32.bf16.bf16.f32 "
        "{%0,%1,%2,%3}, {%4,%5,%6,%7}, {%8,%9}, {%0,%1,%2,%3};\n"
        : "+f"(c0), "+f"(c1), "+f"(c2), "+f"(c3)
        : "r"(a0), "r"(a1), "r"(a2), "r"(a3), "r"(b0), "r"(b1));
}

#define CP_ASYNC16(saddr, gptr) \
    asm volatile("cp.async.cg.shared.global [%0], [%1], 16;\n" :: "r"(saddr), "l"(gptr))
#define CP_COMMIT() asm volatile("cp.async.commit_group;\n" ::)
#define CP_WAIT1()  asm volatile("cp.async.wait_group 1;\n" ::)
#define CP_WAIT0()  asm volatile("cp.async.wait_group 0;\n" ::)

// ---------------------------------------------------------------------------
// Conversion kernel: fp32 -> bf16 hi/lo for q,k,v,Wq,Wk,Wv,Wo
// ---------------------------------------------------------------------------
__global__ __launch_bounds__(256) void convert_kernel(
    const float* __restrict__ q, const float* __restrict__ k, const float* __restrict__ v,
    const float* __restrict__ Wq, const float* __restrict__ Wk,
    const float* __restrict__ Wv, const float* __restrict__ Wo)
{
    size_t e = ((size_t)blockIdx.x * 256 + threadIdx.x) * 4;   // element offset in pool
    const float* src; size_t base;
    if      (e < OFF_K)  { src = q;  base = OFF_Q;  }
    else if (e < OFF_V)  { src = k;  base = OFF_K;  }
    else if (e < OFF_WQ) { src = v;  base = OFF_V;  }
    else if (e < OFF_WK) { src = Wq; base = OFF_WQ; }
    else if (e < OFF_WV) { src = Wk; base = OFF_WK; }
    else if (e < OFF_WO) { src = Wv; base = OFF_WV; }
    else                 { src = Wo; base = OFF_WO; }

    float4 x = *reinterpret_cast<const float4*>(src + (e - base));
    u32 h0, l0, h1, l1;
    cvt_pair(x.x, x.y, h0, l0);
    cvt_pair(x.z, x.w, h1, l1);
    *reinterpret_cast<uint2*>(&g_hi[e]) = make_uint2(h0, h1);
    *reinterpret_cast<uint2*>(&g_lo[e]) = make_uint2(l0, l1);
}

// ---------------------------------------------------------------------------
// Pipelined TC GEMM body.
// smem: 2 stages x 4 arrays (AH, AL, BH, BL), each 128 rows x 16 u32 (pad to 20)
// ---------------------------------------------------------------------------
#define LDSU 20
#define ARR_U32 (128 * LDSU)      // 2560
#define STAGE_U32 (4 * ARR_U32)   // 10240
#define GEMM_SMEM_BYTES (2 * STAGE_U32 * 4)   // 81920

__device__ __forceinline__ void copy_stage(
    u32 sbase_bytes, int stage,
    const __nv_bfloat16* __restrict__ Ah, const __nv_bfloat16* __restrict__ Al,
    const __nv_bfloat16* __restrict__ Bh, const __nv_bfloat16* __restrict__ Bl,
    int r0, int c0, int k0, int tid)
{
    u32 stage_base = sbase_bytes + stage * (STAGE_U32 * 4);
#pragma unroll
    for (int s = 0; s < 8; s++) {
        int arr = s >> 1;                       // 0..3 (compile-time)
        int rc = tid + (s & 1) * 256;           // 0..511
        int row = rc >> 2;                      // 0..127
        int q4 = rc & 3;                        // 16B chunk in row
        const __nv_bfloat16* gsrc;
        int grow;
        if      (arr == 0) { gsrc = Ah; grow = r0 + row; }
        else if (arr == 1) { gsrc = Al; grow = r0 + row; }
        else if (arr == 2) { gsrc = Bh; grow = c0 + row; }
        else               { gsrc = Bl; grow = c0 + row; }
        const void* gptr = gsrc + (size_t)grow * C_ + k0 + q4 * 8;
        u32 saddr = stage_base + arr * (ARR_U32 * 4) + row * (LDSU * 4) + q4 * 16;
        CP_ASYNC16(saddr, gptr);
    }
}

__device__ __forceinline__ void mma_stage(
    const u32* __restrict__ S, int warp_m, int warp_n, int g, int t, float acc[4][4][4])
{
    const u32* AH = S;
    const u32* AL = S + ARR_U32;
    const u32* BH = S + 2 * ARR_U32;
    const u32* BL = S + 3 * ARR_U32;

#pragma unroll
    for (int kk = 0; kk < 2; kk++) {
        const int ko = kk * 8;
        u32 ah[4][4], bh[4][2];
#pragma unroll
        for (int mt = 0; mt < 4; mt++) {
            int m = warp_m + mt * 16;
            ah[mt][0] = AH[(m + g) * LDSU + ko + t];
            ah[mt][1] = AH[(m + g + 8) * LDSU + ko + t];
            ah[mt][2] = AH[(m + g) * LDSU + ko + t + 4];
            ah[mt][3] = AH[(m + g + 8) * LDSU + ko + t + 4];
        }
#pragma unroll
        for (int nt = 0; nt < 4; nt++) {
            int n = warp_n + nt * 8;
            bh[nt][0] = BH[(n + g) * LDSU + ko + t];
            bh[nt][1] = BH[(n + g) * LDSU + ko + t + 4];
        }
#pragma unroll
        for (int mt = 0; mt < 4; mt++)
#pragma unroll
            for (int nt = 0; nt < 4; nt++)
                mma16816(acc[mt][nt][0], acc[mt][nt][1], acc[mt][nt][2], acc[mt][nt][3],
                         ah[mt][0], ah[mt][1], ah[mt][2], ah[mt][3], bh[nt][0], bh[nt][1]);
        {
            u32 bl[4][2];
#pragma unroll
            for (int nt = 0; nt < 4; nt++) {
                int n = warp_n + nt * 8;
                bl[nt][0] = BL[(n + g) * LDSU + ko + t];
                bl[nt][1] = BL[(n + g) * LDSU + ko + t + 4];
            }
#pragma unroll
            for (int mt = 0; mt < 4; mt++)
#pragma unroll
                for (int nt = 0; nt < 4; nt++)
                    mma16816(acc[mt][nt][0], acc[mt][nt][1], acc[mt][nt][2], acc[mt][nt][3],
                             ah[mt][0], ah[mt][1], ah[mt][2], ah[mt][3], bl[nt][0], bl[nt][1]);
        }
        {
            u32 al[4][4];
#pragma unroll
            for (int mt = 0; mt < 4; mt++) {
                int m = warp_m + mt * 16;
                al[mt][0] = AL[(m + g) * LDSU + ko + t];
                al[mt][1] = AL[(m + g + 8) * LDSU + ko + t];
                al[mt][2] = AL[(m + g) * LDSU + ko + t + 4];
                al[mt][3] = AL[(m + g + 8) * LDSU + ko + t + 4];
            }
#pragma unroll
            for (int mt = 0; mt < 4; mt++)
#pragma unroll
                for (int nt = 0; nt < 4; nt++)
                    mma16816(acc[mt][nt][0], acc[mt][nt][1], acc[mt][nt][2], acc[mt][nt][3],
                             al[mt][0], al[mt][1], al[mt][2], al[mt][3], bh[nt][0], bh[nt][1]);
        }
    }
}

__device__ __forceinline__ void gemm_pipe(
    const __nv_bfloat16* __restrict__ Ah, const __nv_bfloat16* __restrict__ Al,
    const __nv_bfloat16* __restrict__ Bh, const __nv_bfloat16* __restrict__ Bl,
    int r0, int c0, u32* sm_u32, float acc[4][4][4])
{
    const int tid = threadIdx.x;
    const int wid = tid >> 5;
    const int lane = tid & 31;
    const int g = lane >> 2;
    const int t = lane & 3;
    const int warp_m = (wid >> 2) * 64;
    const int warp_n = (wid & 3) * 32;

#pragma unroll
    for (int mt = 0; mt < 4; mt++)
#pragma unroll
        for (int nt = 0; nt < 4; nt++)
#pragma unroll
            for (int r = 0; r < 4; r++) acc[mt][nt][r] = 0.f;

    u32 sbase = (u32)__cvta_generic_to_shared(sm_u32);

    // prologue
    copy_stage(sbase, 0, Ah, Al, Bh, Bl, r0, c0, 0, tid);
    CP_COMMIT();

    const int NK = C_ / 32;   // 32
    for (int kt = 0; kt < NK; kt++) {
        if (kt + 1 < NK) {
            copy_stage(sbase, (kt + 1) & 1, Ah, Al, Bh, Bl, r0, c0, (kt + 1) * 32, tid);
            CP_COMMIT();
            CP_WAIT1();
        } else {
            CP_WAIT0();
        }
        __syncthreads();
        mma_stage(sm_u32 + (kt & 1) * STAGE_U32, warp_m, warp_n, g, t, acc);
        __syncthreads();
    }
}

// ---------------------------------------------------------------------------
// QKV projections
// ---------------------------------------------------------------------------
__global__ __launch_bounds__(256, 1) void proj_kernel_tc(
    const float* __restrict__ bq, const float* __restrict__ bk, const float* __restrict__ bv)
{
    extern __shared__ u32 sm_u32[];
    const int which = blockIdx.z;
    const __nv_bfloat16* Ah = g_hi + ((which == 0) ? OFF_Q : (which == 1) ? OFF_K : OFF_V);
    const __nv_bfloat16* Al = g_lo + ((which == 0) ? OFF_Q : (which == 1) ? OFF_K : OFF_V);
    const __nv_bfloat16* Bh = g_hi + ((which == 0) ? OFF_WQ : (which == 1) ? OFF_WK : OFF_WV);
    const __nv_bfloat16* Bl = g_lo + ((which == 0) ? OFF_WQ : (which == 1) ? OFF_WK : OFF_WV);
    const float* bias = (which == 0) ? bq : (which == 1) ? bk : bv;
    float* out        = (which == 0) ? g_qh : (which == 1) ? g_kh : g_vh;

    const int r0 = blockIdx.y * 128;
    const int c0 = blockIdx.x * 128;

    float acc[4][4][4];
    gemm_pipe(Ah, Al, Bh, Bl, r0, c0, sm_u32, acc);

    const int tid = threadIdx.x;
    const int wid = tid >> 5;
    const int lane = tid & 31;
    const int g = lane >> 2;
    const int t = lane & 3;
    const int warp_m = (wid >> 2) * 64;
    const int warp_n = (wid & 3) * 32;

#pragma unroll
    for (int mt = 0; mt < 4; mt++) {
#pragma unroll
        for (int nt = 0; nt < 4; nt++) {
            int gc = c0 + warp_n + nt * 8 + 2 * t;
            int h = gc >> 6, d = gc & 63;
            float bx = bias[gc], by = bias[gc + 1];
#pragma unroll
            for (int half = 0; half < 2; half++) {
                int gr = r0 + warp_m + mt * 16 + g + half * 8;
                int tt = gr >> 1, n = gr & 1;
                float2 o;
                o.x = acc[mt][nt][half * 2 + 0] + bx;
                o.y = acc[mt][nt][half * 2 + 1] + by;
                *reinterpret_cast<float2*>(out + (((size_t)(n * H_ + h) * T_) + tt) * DH_ + d) = o;
            }
        }
    }
}

// ---------------------------------------------------------------------------
// Output projection (A = g_attH/L written by attention)
// ---------------------------------------------------------------------------
__global__ __launch_bounds__(256, 1) void outproj_kernel_tc(
    const float* __restrict__ bo, float* __restrict__ out)
{
    extern __shared__ u32 sm_u32[];
    const int r0 = blockIdx.y * 128;
    const int c0 = blockIdx.x * 128;

    float acc[4][4][4];
    gemm_pipe(g_attH, g_attL, g_hi + OFF_WO, g_lo + OFF_WO, r0, c0, sm_u32, acc);

    const int tid = threadIdx.x;
    const int wid = tid >> 5;
    const int lane = tid & 31;
    const int g = lane >> 2;
    const int t = lane & 3;
    const int warp_m = (wid >> 2) * 64;
    const int warp_n = (wid & 3) * 32;

#pragma unroll
    for (int mt = 0; mt < 4; mt++) {
#pragma unroll
        for (int nt = 0; nt < 4; nt++) {
            int gc = c0 + warp_n + nt * 8 + 2 * t;
            float bx = bo[gc], by = bo[gc + 1];
#pragma unroll
            for (int half = 0; half < 2; half++) {
                int gr = r0 + warp_m + mt * 16 + g + half * 8;
                float2 o;
                o.x = acc[mt][nt][half * 2 + 0] + bx;
                o.y = acc[mt][nt][half * 2 + 1] + by;
                *reinterpret_cast<float2*>(out + (size_t)gr * C_ + gc) = o;
            }
        }
    }
}

// ---------------------------------------------------------------------------
// Flash attention (fp32 FFMA mainloop; epilogue emits bf16 hi/lo)
// ---------------------------------------------------------------------------
__global__ __launch_bounds__(128) void attn_kernel(const int* __restrict__ key_length)
{
    extern __shared__ float sm[];
    float* Qs = sm;
    float* Ks = Qs + 64 * 68;
    float* Vs = Ks + 64 * 68;
    float* Ps = Vs + 64 * 68;

    const int n = blockIdx.z;
    const int h = blockIdx.y;
    const int i0 = blockIdx.x * 64;
    const int kl = key_length[n];

    const int tid = threadIdx.x;
    const int ty = tid >> 4, tx = tid & 15;

    const float* Qg = g_qh + (size_t)(n * H_ + h) * T_ * DH_;
    const float* Kg = g_kh + (size_t)(n * H_ + h) * T_ * DH_;
    const float* Vg = g_vh + (size_t)(n * H_ + h) * T_ * DH_;

#pragma unroll
    for (int it = 0; it < 8; it++) {
        int idx = tid + it * 128;
        int row = idx >> 4;
        int d4 = idx & 15;
        float4 qv = *reinterpret_cast<const float4*>(Qg + (size_t)(i0 + row) * DH_ + d4 * 4);
        Qs[(d4 * 4 + 0) * 68 + row] = qv.x;
        Qs[(d4 * 4 + 1) * 68 + row] = qv.y;
        Qs[(d4 * 4 + 2) * 68 + row] = qv.z;
        Qs[(d4 * 4 + 3) * 68 + row] = qv.w;
    }

    float acc[8][4];
    float m_i[8], l_i[8];
#pragma unroll
    for (int ii = 0; ii < 8; ii++) {
        m_i[ii] = -INFINITY;
        l_i[ii] = 0.f;
#pragma unroll
        for (int dd = 0; dd < 4; dd++) acc[ii][dd] = 0.f;
    }

    for (int j0 = 0; j0 < T_; j0 += 64) {
        bool band = (j0 <= i0 + 63 + WINDOW_) && (j0 + 63 >= i0 - WINDOW_);
        if (!(band || j0 < kl)) continue;

        __syncthreads();

#pragma unroll
        for (int it = 0; it < 8; it++) {
            int idx = tid + it * 128;
            int row = idx >> 4;
            int d4 = idx & 15;
            float4 kv = *reinterpret_cast<const float4*>(Kg + (size_t)(j0 + row) * DH_ + d4 * 4);
            Ks[(d4 * 4 + 0) * 68 + row] = kv.x;
            Ks[(d4 * 4 + 1) * 68 + row] = kv.y;
            Ks[(d4 * 4 + 2) * 68 + row] = kv.z;
            Ks[(d4 * 4 + 3) * 68 + row] = kv.w;
            float4 vv = *reinterpret_cast<const float4*>(Vg + (size_t)(j0 + row) * DH_ + d4 * 4);
            *reinterpret_cast<float4*>(Vs + row * 68 + d4 * 4) = vv;
        }
        __syncthreads();

        float s[8][4];
#pragma unroll
        for (int ii = 0; ii < 8; ii++)
#pragma unroll
            for (int jj = 0; jj < 4; jj++) s[ii][jj] = 0.f;

#pragma unroll 4
        for (int d = 0; d < 64; d++) {
            float4 a0 = *reinterpret_cast<const float4*>(&Qs[d * 68 + ty * 4]);
            float4 a1 = *reinterpret_cast<const float4*>(&Qs[d * 68 + 32 + ty * 4]);
            float4 b  = *reinterpret_cast<const float4*>(&Ks[d * 68 + tx * 4]);
            float a[8] = {a0.x, a0.y, a0.z, a0.w, a1.x, a1.y, a1.z, a1.w};
            float bb[4] = {b.x, b.y, b.z, b.w};
#pragma unroll
            for (int ii = 0; ii < 8; ii++)
#pragma unroll
                for (int jj = 0; jj < 4; jj++) s[ii][jj] = fmaf(a[ii], bb[jj], s[ii][jj]);
        }

#pragma unroll
        for (int ii = 0; ii < 8; ii++) {
            int i = i0 + ((ii < 4) ? (ty * 4 + ii) : (32 + ty * 4 + ii - 4));
#pragma unroll
            for (int jj = 0; jj < 4; jj++) {
                int j = j0 + tx * 4 + jj;
                bool ok = (j < kl) || (j - i <= WINDOW_ && i - j <= WINDOW_);
                s[ii][jj] = ok ? s[ii][jj] * SCALE_ : -1e9f;
            }
        }

        float mt[8];
#pragma unroll
        for (int ii = 0; ii < 8; ii++)
            mt[ii] = fmaxf(fmaxf(s[ii][0], s[ii][1]), fmaxf(s[ii][2], s[ii][3]));
#pragma unroll
        for (int off = 1; off < 16; off <<= 1) {
#pragma unroll
            for (int ii = 0; ii < 8; ii++)
                mt[ii] = fmaxf(mt[ii], __shfl_xor_sync(0xffffffffu, mt[ii], off));
        }

        float corr[8];
#pragma unroll
        for (int ii = 0; ii < 8; ii++) {
            float mn = fmaxf(m_i[ii], mt[ii]);
            corr[ii] = __expf(m_i[ii] - mn);
            m_i[ii] = mn;
        }

        float rs[8];
#pragma unroll
        for (int ii = 0; ii < 8; ii++) {
            int i_loc = (ii < 4) ? (ty * 4 + ii) : (32 + ty * 4 + ii - 4);
            float4 p4;
            p4.x = __expf(s[ii][0] - m_i[ii]);
            p4.y = __expf(s[ii][1] - m_i[ii]);
            p4.z = __expf(s[ii][2] - m_i[ii]);
            p4.w = __expf(s[ii][3] - m_i[ii]);
            *reinterpret_cast<float4*>(&Ps[i_loc * 68 + tx * 4]) = p4;
            rs[ii] = p4.x + p4.y + p4.z + p4.w;
        }
#pragma unroll
        for (int off = 1; off < 16; off <<= 1) {
#pragma unroll
            for (int ii = 0; ii < 8; ii++)
                rs[ii] += __shfl_xor_sync(0xffffffffu, rs[ii], off);
        }
#pragma unroll
        for (int ii = 0; ii < 8; ii++) {
            l_i[ii] = l_i[ii] * corr[ii] + rs[ii];
#pragma unroll
            for (int dd = 0; dd < 4; dd++) acc[ii][dd] *= corr[ii];
        }

        __syncthreads();

#pragma unroll 2
        for (int j4 = 0; j4 < 16; j4++) {
            float4 pa[8];
#pragma unroll
            for (int ii = 0; ii < 8; ii++) {
                int i_loc = (ii < 4) ? (ty * 4 + ii) : (32 + ty * 4 + ii - 4);
                pa[ii] = *reinterpret_cast<const float4*>(&Ps[i_loc * 68 + j4 * 4]);
            }
#pragma unroll
            for (int ju = 0; ju < 4; ju++) {
                float4 b = *reinterpret_cast<const float4*>(&Vs[(j4 * 4 + ju) * 68 + tx * 4]);
                float pv[8] = {pa[0].x, pa[1].x, pa[2].x, pa[3].x, pa[4].x, pa[5].x, pa[6].x, pa[7].x};
                if (ju == 1) { pv[0]=pa[0].y; pv[1]=pa[1].y; pv[2]=pa[2].y; pv[3]=pa[3].y; pv[4]=pa[4].y; pv[5]=pa[5].y; pv[6]=pa[6].y; pv[7]=pa[7].y; }
                else if (ju == 2) { pv[0]=pa[0].z; pv[1]=pa[1].z; pv[2]=pa[2].z; pv[3]=pa[3].z; pv[4]=pa[4].z; pv[5]=pa[5].z; pv[6]=pa[6].z; pv[7]=pa[7].z; }
                else if (ju == 3) { pv[0]=pa[0].w; pv[1]=pa[1].w; pv[2]=pa[2].w; pv[3]=pa[3].w; pv[4]=pa[4].w; pv[5]=pa[5].w; pv[6]=pa[6].w; pv[7]=pa[7].w; }
#pragma unroll
                for (int ii = 0; ii < 8; ii++) {
                    acc[ii][0] = fmaf(pv[ii], b.x, acc[ii][0]);
                    acc[ii][1] = fmaf(pv[ii], b.y, acc[ii][1]);
                    acc[ii][2] = fmaf(pv[ii], b.z, acc[ii][2]);
                    acc[ii][3] = fmaf(pv[ii], b.w, acc[ii][3]);
                }
            }
        }
    }

    // Epilogue: emit bf16 hi/lo for outproj
#pragma unroll
    for (int ii = 0; ii < 8; ii++) {
        int i_loc = (ii < 4) ? (ty * 4 + ii) : (32 + ty * 4 + ii - 4);
        int i = i0 + i_loc;
        float inv = 1.f / l_i[ii];
        float ox = acc[ii][0] * inv;
        float oy = acc[ii][1] * inv;
        float oz = acc[ii][2] * inv;
        float ow = acc[ii][3] * inv;
        u32 h0, l0, h1, l1;
        cvt_pair(ox, oy, h0, l0);
        cvt_pair(oz, ow, h1, l1);
        size_t rowbase = ((size_t)i * N_ + n) * C_ + h * DH_ + tx * 4;
        *reinterpret_cast<uint2*>(&g_attH[rowbase]) = make_uint2(h0, h1);
        *reinterpret_cast<uint2*>(&g_attL[rowbase]) = make_uint2(l0, l1);
    }
}

extern "C" void kernel_launch(void* const* d_in, const int* in_sizes, int n_in,
                              void* d_out, int out_size)
{
    const float* q  = (const float*)d_in[0];
    const float* k  = (const float*)d_in[1];
    const float* v  = (const float*)d_in[2];
    const float* Wq = (const float*)d_in[3];
    const float* bq = (const float*)d_in[4];
    const float* Wk = (const float*)d_in[5];
    const float* bk = (const float*)d_in[6];
    const float* Wv = (const float*)d_in[7];
    const float* bv = (const float*)d_in[8];
    const float* Wo = (const float*)d_in[9];
    const float* bo = (const float*)d_in[10];
    const int* key_length = (const int*)d_in[11];
    float* out = (float*)d_out;

    // 1. Pre-convert q,k,v + weights to bf16 hi/lo
    convert_kernel<<<TOTAL_CVT / 4 / 256, 256>>>(q, k, v, Wq, Wk, Wv, Wo);

    // 2. QKV projections (tensor-core, pipelined)
    cudaFuncSetAttribute(proj_kernel_tc, cudaFuncAttributeMaxDynamicSharedMemorySize, GEMM_SMEM_BYTES);
    dim3 gproj(C_ / 128, M_ / 128, 3);
    proj_kernel_tc<<<gproj, 256, GEMM_SMEM_BYTES>>>(bq, bk, bv);

    // 3. Attention
    const int attn_smem = 4 * 64 * 68 * (int)sizeof(float);
    cudaFuncSetAttribute(attn_kernel, cudaFuncAttributeMaxDynamicSharedMemorySize, attn_smem);
    dim3 gattn(T_ / 64, H_, N_);
    attn_kernel<<<gattn, 128, attn_smem>>>(key_length);

    // 4. Output projection
    cudaFuncSetAttribute(outproj_kernel_tc, cudaFuncAttributeMaxDynamicSharedMemorySize, GEMM_SMEM_BYTES);
    dim3 gout(C_ / 128, M_ / 128);
    outproj_kernel_tc<<<gout, 256, GEMM_SMEM_BYTES>>>(bo, out);
}

// round 6
// speedup vs baseline: 2.2681x; 1.3600x over previous
#include <cuda_runtime.h>
#include <cuda_bf16.h>
#include <math.h>

#define T_ 2048
#define N_ 2
#define C_ 1024
#define H_ 16
#define DH_ 64
#define M_ (T_ * N_)
#define WINDOW_ 128
#define SCALE_ 0.125f

typedef unsigned int u32;

// Pre-converted bf16 hi/lo pool: [q | k | v | Wq | Wk | Wv | Wo]
#define OFF_Q  0
#define OFF_K  4194304
#define OFF_V  8388608
#define OFF_WQ 12582912
#define OFF_WK 13631488
#define OFF_WV 14680064
#define OFF_WO 15728640
#define TOTAL_CVT 16777216
__device__ __align__(16) __nv_bfloat16 g_hi[TOTAL_CVT];
__device__ __align__(16) __nv_bfloat16 g_lo[TOTAL_CVT];

// projected q/k: [nh][t][d] bf16 hi/lo ; projected v transposed: [nh][d][t]
__device__ __align__(16) __nv_bfloat16 g_qH[N_ * H_ * T_ * DH_];
__device__ __align__(16) __nv_bfloat16 g_qL[N_ * H_ * T_ * DH_];
__device__ __align__(16) __nv_bfloat16 g_kH[N_ * H_ * T_ * DH_];
__device__ __align__(16) __nv_bfloat16 g_kL[N_ * H_ * T_ * DH_];
__device__ __align__(16) __nv_bfloat16 g_vTH[N_ * H_ * DH_ * T_];
__device__ __align__(16) __nv_bfloat16 g_vTL[N_ * H_ * DH_ * T_];

// attention output, bf16 hi/lo (row-major 4096 x 1024, row = t*2+n)
__device__ __align__(16) __nv_bfloat16 g_attH[M_ * C_];
__device__ __align__(16) __nv_bfloat16 g_attL[M_ * C_];

// ---------------------------------------------------------------------------
// helpers
// ---------------------------------------------------------------------------
__device__ __forceinline__ void cvt_pair(float x, float y, u32& hi, u32& lo) {
    __nv_bfloat16 hx = __float2bfloat16_rn(x);
    __nv_bfloat16 hy = __float2bfloat16_rn(y);
    float rx = x - __bfloat162float(hx);
    float ry = y - __bfloat162float(hy);
    __nv_bfloat16 lx = __float2bfloat16_rn(rx);
    __nv_bfloat16 ly = __float2bfloat16_rn(ry);
    __nv_bfloat162 Hh; Hh.x = hx; Hh.y = hy;
    __nv_bfloat162 Ll; Ll.x = lx; Ll.y = ly;
    hi = *reinterpret_cast<u32*>(&Hh);
    lo = *reinterpret_cast<u32*>(&Ll);
}

__device__ __forceinline__ void mma16816(float& c0, float& c1, float& c2, float& c3,
                                         u32 a0, u32 a1, u32 a2, u32 a3, u32 b0, u32 b1) {
    asm volatile(
        "mma.sync.aligned.m16n8k16.row.col.f32.bf16.bf16.f32 "
        "{%0,%1,%2,%3}, {%4,%5,%6,%7}, {%8,%9}, {%0,%1,%2,%3};\n"
        : "+f"(c0), "+f"(c1), "+f"(c2), "+f"(c3)
        : "r"(a0), "r"(a1), "r"(a2), "r"(a3), "r"(b0), "r"(b1));
}

#define CP_ASYNC16(saddr, gptr) \
    asm volatile("cp.async.cg.shared.global [%0], [%1], 16;\n" :: "r"(saddr), "l"(gptr))
#define CP_COMMIT() asm volatile("cp.async.commit_group;\n" ::)
#define CP_WAIT1()  asm volatile("cp.async.wait_group 1;\n" ::)
#define CP_WAIT0()  asm volatile("cp.async.wait_group 0;\n" ::)

// ---------------------------------------------------------------------------
// Conversion kernel: fp32 -> bf16 hi/lo for q,k,v,Wq,Wk,Wv,Wo
// ---------------------------------------------------------------------------
__global__ __launch_bounds__(256) void convert_kernel(
    const float* __restrict__ q, const float* __restrict__ k, const float* __restrict__ v,
    const float* __restrict__ Wq, const float* __restrict__ Wk,
    const float* __restrict__ Wv, const float* __restrict__ Wo)
{
    size_t e = ((size_t)blockIdx.x * 256 + threadIdx.x) * 4;
    const float* src; size_t base;
    if      (e < OFF_K)  { src = q;  base = OFF_Q;  }
    else if (e < OFF_V)  { src = k;  base = OFF_K;  }
    else if (e < OFF_WQ) { src = v;  base = OFF_V;  }
    else if (e < OFF_WK) { src = Wq; base = OFF_WQ; }
    else if (e < OFF_WV) { src = Wk; base = OFF_WK; }
    else if (e < OFF_WO) { src = Wv; base = OFF_WV; }
    else                 { src = Wo; base = OFF_WO; }

    float4 x = *reinterpret_cast<const float4*>(src + (e - base));
    u32 h0, l0, h1, l1;
    cvt_pair(x.x, x.y, h0, l0);
    cvt_pair(x.z, x.w, h1, l1);
    *reinterpret_cast<uint2*>(&g_hi[e]) = make_uint2(h0, h1);
    *reinterpret_cast<uint2*>(&g_lo[e]) = make_uint2(l0, l1);
}

// ---------------------------------------------------------------------------
// Pipelined TC GEMM body (same as R5)
// ---------------------------------------------------------------------------
#define LDSU 20
#define ARR_U32 (128 * LDSU)
#define STAGE_U32 (4 * ARR_U32)
#define GEMM_SMEM_BYTES (2 * STAGE_U32 * 4)

__device__ __forceinline__ void copy_stage(
    u32 sbase_bytes, int stage,
    const __nv_bfloat16* __restrict__ Ah, const __nv_bfloat16* __restrict__ Al,
    const __nv_bfloat16* __restrict__ Bh, const __nv_bfloat16* __restrict__ Bl,
    int r0, int c0, int k0, int tid)
{
    u32 stage_base = sbase_bytes + stage * (STAGE_U32 * 4);
#pragma unroll
    for (int s = 0; s < 8; s++) {
        int arr = s >> 1;
        int rc = tid + (s & 1) * 256;
        int row = rc >> 2;
        int q4 = rc & 3;
        const __nv_bfloat16* gsrc;
        int grow;
        if      (arr == 0) { gsrc = Ah; grow = r0 + row; }
        else if (arr == 1) { gsrc = Al; grow = r0 + row; }
        else if (arr == 2) { gsrc = Bh; grow = c0 + row; }
        else               { gsrc = Bl; grow = c0 + row; }
        const void* gptr = gsrc + (size_t)grow * C_ + k0 + q4 * 8;
        u32 saddr = stage_base + arr * (ARR_U32 * 4) + row * (LDSU * 4) + q4 * 16;
        CP_ASYNC16(saddr, gptr);
    }
}

__device__ __forceinline__ void mma_stage(
    const u32* __restrict__ S, int warp_m, int warp_n, int g, int t, float acc[4][4][4])
{
    const u32* AH = S;
    const u32* AL = S + ARR_U32;
    const u32* BH = S + 2 * ARR_U32;
    const u32* BL = S + 3 * ARR_U32;

#pragma unroll
    for (int kk = 0; kk < 2; kk++) {
        const int ko = kk * 8;
        u32 ah[4][4], bh[4][2];
#pragma unroll
        for (int mt = 0; mt < 4; mt++) {
            int m = warp_m + mt * 16;
            ah[mt][0] = AH[(m + g) * LDSU + ko + t];
            ah[mt][1] = AH[(m + g + 8) * LDSU + ko + t];
            ah[mt][2] = AH[(m + g) * LDSU + ko + t + 4];
            ah[mt][3] = AH[(m + g + 8) * LDSU + ko + t + 4];
        }
#pragma unroll
        for (int nt = 0; nt < 4; nt++) {
            int n = warp_n + nt * 8;
            bh[nt][0] = BH[(n + g) * LDSU + ko + t];
            bh[nt][1] = BH[(n + g) * LDSU + ko + t + 4];
        }
#pragma unroll
        for (int mt = 0; mt < 4; mt++)
#pragma unroll
            for (int nt = 0; nt < 4; nt++)
                mma16816(acc[mt][nt][0], acc[mt][nt][1], acc[mt][nt][2], acc[mt][nt][3],
                         ah[mt][0], ah[mt][1], ah[mt][2], ah[mt][3], bh[nt][0], bh[nt][1]);
        {
            u32 bl[4][2];
#pragma unroll
            for (int nt = 0; nt < 4; nt++) {
                int n = warp_n + nt * 8;
                bl[nt][0] = BL[(n + g) * LDSU + ko + t];
                bl[nt][1] = BL[(n + g) * LDSU + ko + t + 4];
            }
#pragma unroll
            for (int mt = 0; mt < 4; mt++)
#pragma unroll
                for (int nt = 0; nt < 4; nt++)
                    mma16816(acc[mt][nt][0], acc[mt][nt][1], acc[mt][nt][2], acc[mt][nt][3],
                             ah[mt][0], ah[mt][1], ah[mt][2], ah[mt][3], bl[nt][0], bl[nt][1]);
        }
        {
            u32 al[4][4];
#pragma unroll
            for (int mt = 0; mt < 4; mt++) {
                int m = warp_m + mt * 16;
                al[mt][0] = AL[(m + g) * LDSU + ko + t];
                al[mt][1] = AL[(m + g + 8) * LDSU + ko + t];
                al[mt][2] = AL[(m + g) * LDSU + ko + t + 4];
                al[mt][3] = AL[(m + g + 8) * LDSU + ko + t + 4];
            }
#pragma unroll
            for (int mt = 0; mt < 4; mt++)
#pragma unroll
                for (int nt = 0; nt < 4; nt++)
                    mma16816(acc[mt][nt][0], acc[mt][nt][1], acc[mt][nt][2], acc[mt][nt][3],
                             al[mt][0], al[mt][1], al[mt][2], al[mt][3], bh[nt][0], bh[nt][1]);
        }
    }
}

__device__ __forceinline__ void gemm_pipe(
    const __nv_bfloat16* __restrict__ Ah, const __nv_bfloat16* __restrict__ Al,
    const __nv_bfloat16* __restrict__ Bh, const __nv_bfloat16* __restrict__ Bl,
    int r0, int c0, u32* sm_u32, float acc[4][4][4])
{
    const int tid = threadIdx.x;
    const int wid = tid >> 5;
    const int lane = tid & 31;
    const int g = lane >> 2;
    const int t = lane & 3;
    const int warp_m = (wid >> 2) * 64;
    const int warp_n = (wid & 3) * 32;

#pragma unroll
    for (int mt = 0; mt < 4; mt++)
#pragma unroll
        for (int nt = 0; nt < 4; nt++)
#pragma unroll
            for (int r = 0; r < 4; r++) acc[mt][nt][r] = 0.f;

    u32 sbase = (u32)__cvta_generic_to_shared(sm_u32);
    copy_stage(sbase, 0, Ah, Al, Bh, Bl, r0, c0, 0, tid);
    CP_COMMIT();

    const int NK = C_ / 32;
    for (int kt = 0; kt < NK; kt++) {
        if (kt + 1 < NK) {
            copy_stage(sbase, (kt + 1) & 1, Ah, Al, Bh, Bl, r0, c0, (kt + 1) * 32, tid);
            CP_COMMIT();
            CP_WAIT1();
        } else {
            CP_WAIT0();
        }
        __syncthreads();
        mma_stage(sm_u32 + (kt & 1) * STAGE_U32, warp_m, warp_n, g, t, acc);
        __syncthreads();
    }
}

// ---------------------------------------------------------------------------
// QKV projections — epilogue emits bf16 hi/lo; V transposed
// ---------------------------------------------------------------------------
__global__ __launch_bounds__(256, 1) void proj_kernel_tc(
    const float* __restrict__ bq, const float* __restrict__ bk, const float* __restrict__ bv)
{
    extern __shared__ u32 sm_u32[];
    const int which = blockIdx.z;
    const __nv_bfloat16* Ah = g_hi + ((which == 0) ? OFF_Q : (which == 1) ? OFF_K : OFF_V);
    const __nv_bfloat16* Al = g_lo + ((which == 0) ? OFF_Q : (which == 1) ? OFF_K : OFF_V);
    const __nv_bfloat16* Bh = g_hi + ((which == 0) ? OFF_WQ : (which == 1) ? OFF_WK : OFF_WV);
    const __nv_bfloat16* Bl = g_lo + ((which == 0) ? OFF_WQ : (which == 1) ? OFF_WK : OFF_WV);
    const float* bias = (which == 0) ? bq : (which == 1) ? bk : bv;

    const int r0 = blockIdx.y * 128;
    const int c0 = blockIdx.x * 128;

    float acc[4][4][4];
    gemm_pipe(Ah, Al, Bh, Bl, r0, c0, sm_u32, acc);

    const int tid = threadIdx.x;
    const int wid = tid >> 5;
    const int lane = tid & 31;
    const int g = lane >> 2;
    const int t = lane & 3;
    const int warp_m = (wid >> 2) * 64;
    const int warp_n = (wid & 3) * 32;

    __nv_bfloat16* OH = (which == 0) ? g_qH : g_kH;
    __nv_bfloat16* OL = (which == 0) ? g_qL : g_kL;

#pragma unroll
    for (int mt = 0; mt < 4; mt++) {
#pragma unroll
        for (int nt = 0; nt < 4; nt++) {
            int gc = c0 + warp_n + nt * 8 + 2 * t;
            int hh = gc >> 6, d = gc & 63;
            float bx = bias[gc], by = bias[gc + 1];
#pragma unroll
            for (int half = 0; half < 2; half++) {
                int gr = r0 + warp_m + mt * 16 + g + half * 8;
                int tt = gr >> 1, nn = gr & 1;
                int nh = nn * H_ + hh;
                float ox = acc[mt][nt][half * 2 + 0] + bx;
                float oy = acc[mt][nt][half * 2 + 1] + by;
                u32 phi, plo;
                cvt_pair(ox, oy, phi, plo);
                if (which < 2) {
                    size_t idx = ((size_t)nh * T_ + tt) * DH_ + d;
                    *reinterpret_cast<u32*>(&OH[idx]) = phi;
                    *reinterpret_cast<u32*>(&OL[idx]) = plo;
                } else {
                    __nv_bfloat162 H2 = *reinterpret_cast<__nv_bfloat162*>(&phi);
                    __nv_bfloat162 L2 = *reinterpret_cast<__nv_bfloat162*>(&plo);
                    size_t base = ((size_t)nh * DH_ + d) * T_ + tt;
                    g_vTH[base]      = H2.x;
                    g_vTH[base + T_] = H2.y;
                    g_vTL[base]      = L2.x;
                    g_vTL[base + T_] = L2.y;
                }
            }
        }
    }
}

// ---------------------------------------------------------------------------
// Output projection (unchanged)
// ---------------------------------------------------------------------------
__global__ __launch_bounds__(256, 1) void outproj_kernel_tc(
    const float* __restrict__ bo, float* __restrict__ out)
{
    extern __shared__ u32 sm_u32[];
    const int r0 = blockIdx.y * 128;
    const int c0 = blockIdx.x * 128;

    float acc[4][4][4];
    gemm_pipe(g_attH, g_attL, g_hi + OFF_WO, g_lo + OFF_WO, r0, c0, sm_u32, acc);

    const int tid = threadIdx.x;
    const int wid = tid >> 5;
    const int lane = tid & 31;
    const int g = lane >> 2;
    const int t = lane & 3;
    const int warp_m = (wid >> 2) * 64;
    const int warp_n = (wid & 3) * 32;

#pragma unroll
    for (int mt = 0; mt < 4; mt++) {
#pragma unroll
        for (int nt = 0; nt < 4; nt++) {
            int gc = c0 + warp_n + nt * 8 + 2 * t;
            float bx = bo[gc], by = bo[gc + 1];
#pragma unroll
            for (int half = 0; half < 2; half++) {
                int gr = r0 + warp_m + mt * 16 + g + half * 8;
                float2 o;
                o.x = acc[mt][nt][half * 2 + 0] + bx;
                o.y = acc[mt][nt][half * 2 + 1] + by;
                *reinterpret_cast<float2*>(out + (size_t)gr * C_ + gc) = o;
            }
        }
    }
}

// ---------------------------------------------------------------------------
// Tensor-core flash attention.
// Block: 64 q rows, 4 warps (16 rows each), 128 threads, Dh=64 in registers.
// Smem (u32): QH[64*36] @0, QL @2304, stages@4608: {KH,KL,VH,VL} x2 (9216 u32/stage)
// ---------------------------------------------------------------------------
#define AST 36
#define ATTN_SMEM_BYTES 92160

__global__ __launch_bounds__(128, 2) void attn_tc(const int* __restrict__ key_length)
{
    extern __shared__ u32 smu[];
    const int n = blockIdx.z, hidx = blockIdx.y, i0 = blockIdx.x * 64;
    const int nh = n * H_ + hidx;
    const int kl = key_length[n];
    const int tid = threadIdx.x;
    const int w = tid >> 5, lane = tid & 31, g = lane >> 2, t = lane & 3;

    const __nv_bfloat16* QHg = g_qH + (size_t)nh * T_ * DH_;
    const __nv_bfloat16* QLg = g_qL + (size_t)nh * T_ * DH_;
    const __nv_bfloat16* KHg = g_kH + (size_t)nh * T_ * DH_;
    const __nv_bfloat16* KLg = g_kL + (size_t)nh * T_ * DH_;
    const __nv_bfloat16* VHg = g_vTH + (size_t)nh * DH_ * T_;
    const __nv_bfloat16* VLg = g_vTL + (size_t)nh * DH_ * T_;

    u32 sbase = (u32)__cvta_generic_to_shared(smu);

    // Q tiles (hi @0, lo @9216 bytes)
#pragma unroll
    for (int i = 0; i < 4; i++) {
        int c = tid + i * 128;
        int row = c >> 3, q8 = c & 7;
        CP_ASYNC16(sbase + row * 144 + q8 * 16, QHg + (size_t)(i0 + row) * DH_ + q8 * 8);
        CP_ASYNC16(sbase + 9216 + row * 144 + q8 * 16, QLg + (size_t)(i0 + row) * DH_ + q8 * 8);
    }

    // first tile j=0 is always active (key_length >= 1)
    {
        u32 base = sbase + 18432;
#pragma unroll
        for (int i = 0; i < 4; i++) {
            int c = tid + i * 128;
            int row = c >> 3, q8 = c & 7;
            u32 so = base + row * 144 + q8 * 16;
            CP_ASYNC16(so,         KHg + (size_t)row * DH_ + q8 * 8);
            CP_ASYNC16(so + 9216,  KLg + (size_t)row * DH_ + q8 * 8);
            CP_ASYNC16(so + 18432, VHg + (size_t)row * T_ + q8 * 8);
            CP_ASYNC16(so + 27648, VLg + (size_t)row * T_ + q8 * 8);
        }
    }
    CP_COMMIT();

    float o[8][4];
#pragma unroll
    for (int dt = 0; dt < 8; dt++)
#pragma unroll
        for (int r = 0; r < 4; r++) o[dt][r] = 0.f;
    float m_g = -INFINITY, m_h = -INFINITY, l_g = 0.f, l_h = 0.f;
    u32 qfh[4][4], qfl[4][4];

    const int i_g = i0 + w * 16 + g;
    const int i_h8 = i_g + 8;

    bool first = true;
    int jcur = 0, stage = 0;
    while (jcur < T_) {
        // next active tile
        int jn = jcur + 64;
        while (jn < T_) {
            if (jn < kl) break;
            if (jn <= i0 + 63 + WINDOW_ && jn + 63 >= i0 - WINDOW_) break;
            jn += 64;
        }
        if (jn < T_) {
            u32 base = sbase + 18432 + (stage ^ 1) * 36864;
#pragma unroll
            for (int i = 0; i < 4; i++) {
                int c = tid + i * 128;
                int row = c >> 3, q8 = c & 7;
                u32 so = base + row * 144 + q8 * 16;
                CP_ASYNC16(so,         KHg + (size_t)(jn + row) * DH_ + q8 * 8);
                CP_ASYNC16(so + 9216,  KLg + (size_t)(jn + row) * DH_ + q8 * 8);
                CP_ASYNC16(so + 18432, VHg + (size_t)row * T_ + jn + q8 * 8);
                CP_ASYNC16(so + 27648, VLg + (size_t)row * T_ + jn + q8 * 8);
            }
            CP_COMMIT();
            CP_WAIT1();
        } else {
            CP_WAIT0();
        }
        __syncthreads();

        if (first) {
            first = false;
            const int mrow = w * 16;
#pragma unroll
            for (int ks = 0; ks < 4; ks++) {
                qfh[ks][0] = smu[(mrow + g) * AST + ks * 8 + t];
                qfh[ks][1] = smu[(mrow + g + 8) * AST + ks * 8 + t];
                qfh[ks][2] = smu[(mrow + g) * AST + ks * 8 + t + 4];
                qfh[ks][3] = smu[(mrow + g + 8) * AST + ks * 8 + t + 4];
                qfl[ks][0] = smu[2304 + (mrow + g) * AST + ks * 8 + t];
                qfl[ks][1] = smu[2304 + (mrow + g + 8) * AST + ks * 8 + t];
                qfl[ks][2] = smu[2304 + (mrow + g) * AST + ks * 8 + t + 4];
                qfl[ks][3] = smu[2304 + (mrow + g + 8) * AST + ks * 8 + t + 4];
            }
        }

        const u32* KS = smu + 4608 + stage * 9216;
        const u32* KH = KS;
        const u32* KL = KS + 2304;
        const u32* VH = KS + 4608;
        const u32* VL = KS + 6912;

        // S = Q K^T (3 split terms)
        float s[8][4];
#pragma unroll
        for (int nt = 0; nt < 8; nt++)
#pragma unroll
            for (int r = 0; r < 4; r++) s[nt][r] = 0.f;

#pragma unroll
        for (int ks = 0; ks < 4; ks++) {
#pragma unroll
            for (int nt = 0; nt < 8; nt++) {
                int br = (8 * nt + g) * AST + ks * 8 + t;
                u32 b0h = KH[br], b1h = KH[br + 4];
                u32 b0l = KL[br], b1l = KL[br + 4];
                mma16816(s[nt][0], s[nt][1], s[nt][2], s[nt][3],
                         qfh[ks][0], qfh[ks][1], qfh[ks][2], qfh[ks][3], b0h, b1h);
                mma16816(s[nt][0], s[nt][1], s[nt][2], s[nt][3],
                         qfh[ks][0], qfh[ks][1], qfh[ks][2], qfh[ks][3], b0l, b1l);
                mma16816(s[nt][0], s[nt][1], s[nt][2], s[nt][3],
                         qfl[ks][0], qfl[ks][1], qfl[ks][2], qfl[ks][3], b0h, b1h);
            }
        }

        // mask + scale
#pragma unroll
        for (int nt = 0; nt < 8; nt++) {
            int jb = jcur + 8 * nt + 2 * t;
#pragma unroll
            for (int c = 0; c < 4; c++) {
                int j = jb + (c & 1);
                int i = (c < 2) ? i_g : i_h8;
                bool ok = (j < kl) || (j - i <= WINDOW_ && i - j <= WINDOW_);
                s[nt][c] = ok ? s[nt][c] * SCALE_ : -1e9f;
            }
        }

        // row max over 64 cols: intra-thread then across t lanes (xor 1,2)
        float mg = -1e30f, mh = -1e30f;
#pragma unroll
        for (int nt = 0; nt < 8; nt++) {
            mg = fmaxf(mg, fmaxf(s[nt][0], s[nt][1]));
            mh = fmaxf(mh, fmaxf(s[nt][2], s[nt][3]));
        }
        mg = fmaxf(mg, __shfl_xor_sync(0xffffffffu, mg, 1));
        mg = fmaxf(mg, __shfl_xor_sync(0xffffffffu, mg, 2));
        mh = fmaxf(mh, __shfl_xor_sync(0xffffffffu, mh, 1));
        mh = fmaxf(mh, __shfl_xor_sync(0xffffffffu, mh, 2));

        float mng = fmaxf(m_g, mg), mnh = fmaxf(m_h, mh);
        float cg = __expf(m_g - mng), ch = __expf(m_h - mnh);
        m_g = mng; m_h = mnh;

        // P = exp(S - m), pack to bf16 hi/lo, row sums
        float rg = 0.f, rh = 0.f;
        u32 ph[8][2], pl[8][2];
#pragma unroll
        for (int nt = 0; nt < 8; nt++) {
            float p0 = __expf(s[nt][0] - m_g);
            float p1 = __expf(s[nt][1] - m_g);
            float p2 = __expf(s[nt][2] - m_h);
            float p3 = __expf(s[nt][3] - m_h);
            rg += p0 + p1; rh += p2 + p3;
            cvt_pair(p0, p1, ph[nt][0], pl[nt][0]);
            cvt_pair(p2, p3, ph[nt][1], pl[nt][1]);
        }
        rg += __shfl_xor_sync(0xffffffffu, rg, 1);
        rg += __shfl_xor_sync(0xffffffffu, rg, 2);
        rh += __shfl_xor_sync(0xffffffffu, rh, 1);
        rh += __shfl_xor_sync(0xffffffffu, rh, 2);
        l_g = l_g * cg + rg;
        l_h = l_h * ch + rh;
#pragma unroll
        for (int dt = 0; dt < 8; dt++) {
            o[dt][0] *= cg; o[dt][1] *= cg;
            o[dt][2] *= ch; o[dt][3] *= ch;
        }

        // O += P V (P as A-fragments straight from registers)
#pragma unroll
        for (int ks = 0; ks < 4; ks++) {
            u32 aH0 = ph[2 * ks][0], aH1 = ph[2 * ks][1], aH2 = ph[2 * ks + 1][0], aH3 = ph[2 * ks + 1][1];
            u32 aL0 = pl[2 * ks][0], aL1 = pl[2 * ks][1], aL2 = pl[2 * ks + 1][0], aL3 = pl[2 * ks + 1][1];
#pragma unroll
            for (int dt = 0; dt < 8; dt++) {
                int br = (8 * dt + g) * AST + ks * 8 + t;
                u32 b0h = VH[br], b1h = VH[br + 4];
                u32 b0l = VL[br], b1l = VL[br + 4];
                mma16816(o[dt][0], o[dt][1], o[dt][2], o[dt][3], aH0, aH1, aH2, aH3, b0h, b1h);
                mma16816(o[dt][0], o[dt][1], o[dt][2], o[dt][3], aH0, aH1, aH2, aH3, b0l, b1l);
                mma16816(o[dt][0], o[dt][1], o[dt][2], o[dt][3], aL0, aL1, aL2, aL3, b0h, b1h);
            }
        }
        __syncthreads();
        stage ^= 1;
        jcur = jn;
    }

    // Epilogue: O/l -> bf16 hi/lo into g_att
    float ig = 1.f / l_g, ih = 1.f / l_h;
#pragma unroll
    for (int dt = 0; dt < 8; dt++) {
        int col = 8 * dt + 2 * t;
        u32 phi, plo;
        cvt_pair(o[dt][0] * ig, o[dt][1] * ig, phi, plo);
        size_t rb = ((size_t)i_g * N_ + n) * C_ + hidx * DH_ + col;
        *reinterpret_cast<u32*>(&g_attH[rb]) = phi;
        *reinterpret_cast<u32*>(&g_attL[rb]) = plo;
        cvt_pair(o[dt][2] * ih, o[dt][3] * ih, phi, plo);
        size_t rb2 = ((size_t)i_h8 * N_ + n) * C_ + hidx * DH_ + col;
        *reinterpret_cast<u32*>(&g_attH[rb2]) = phi;
        *reinterpret_cast<u32*>(&g_attL[rb2]) = plo;
    }
}

extern "C" void kernel_launch(void* const* d_in, const int* in_sizes, int n_in,
                              void* d_out, int out_size)
{
    const float* q  = (const float*)d_in[0];
    const float* k  = (const float*)d_in[1];
    const float* v  = (const float*)d_in[2];
    const float* bq = (const float*)d_in[4];
    const float* bk = (const float*)d_in[6];
    const float* bv = (const float*)d_in[8];
    const float* bo = (const float*)d_in[10];
    const float* Wq = (const float*)d_in[3];
    const float* Wk = (const float*)d_in[5];
    const float* Wv = (const float*)d_in[7];
    const float* Wo = (const float*)d_in[9];
    const int* key_length = (const int*)d_in[11];
    float* out = (float*)d_out;

    // 1. Pre-convert inputs + weights to bf16 hi/lo
    convert_kernel<<<TOTAL_CVT / 4 / 256, 256>>>(q, k, v, Wq, Wk, Wv, Wo);

    // 2. QKV projections
    cudaFuncSetAttribute(proj_kernel_tc, cudaFuncAttributeMaxDynamicSharedMemorySize, GEMM_SMEM_BYTES);
    dim3 gproj(C_ / 128, M_ / 128, 3);
    proj_kernel_tc<<<gproj, 256, GEMM_SMEM_BYTES>>>(bq, bk, bv);

    // 3. Tensor-core flash attention
    cudaFuncSetAttribute(attn_tc, cudaFuncAttributeMaxDynamicSharedMemorySize, ATTN_SMEM_BYTES);
    dim3 gattn(T_ / 64, H_, N_);
    attn_tc<<<gattn, 128, ATTN_SMEM_BYTES>>>(key_length);

    // 4. Output projection
    cudaFuncSetAttribute(outproj_kernel_tc, cudaFuncAttributeMaxDynamicSharedMemorySize, GEMM_SMEM_BYTES);
    dim3 gout(C_ / 128, M_ / 128);
    outproj_kernel_tc<<<gout, 256, GEMM_SMEM_BYTES>>>(bo, out);
}